// round 1
// baseline (speedup 1.0000x reference)
#include <cuda_runtime.h>
#include <math.h>
#include <stdint.h>

// Problem constants
#define Bb   4
#define Tt   1024
#define Dd   1024
#define Hh   16
#define HSs  64
#define Ll   4
#define FFf  4096
#define Vv   32000
#define BT   (Bb*Tt)          // 4096
#define EPSf 1e-5f

// ---------------- scratch (device globals; no allocs allowed) ----------------
__device__ float g_x[BT*Dd];
__device__ float g_h[BT*Dd];
__device__ float g_q[BT*Dd];
__device__ float g_k[BT*Dd];
__device__ float g_v[BT*Dd];
__device__ float g_o[BT*Dd];
__device__ float g_ff[(size_t)BT*FFf];
__device__ float g_logits[(size_t)BT*Vv];
__device__ float g_rownll[BT];

// ---------------- embed: x = tok_emb[idx] + pos_emb ----------------
__global__ void embed_kernel(const int* __restrict__ idx,
                             const float* __restrict__ tok,
                             const float* __restrict__ pos) {
    size_t i = (size_t)blockIdx.x * 256 + threadIdx.x;   // BT*Dd total
    int d  = (int)(i & (Dd - 1));
    int bt = (int)(i >> 10);
    int t  = bt & (Tt - 1);
    g_x[i] = tok[(size_t)idx[bt] * Dd + d] + pos[(size_t)t * Dd + d];
}

// ---------------- layernorm: one block per row ----------------
__global__ void ln_kernel(const float* __restrict__ x,
                          const float* __restrict__ g,
                          const float* __restrict__ b,
                          float* __restrict__ out) {
    __shared__ float s1[256], s2[256];
    int row = blockIdx.x;
    const float* xr = x + (size_t)row * Dd;
    int tid = threadIdx.x;
    float a = 0.f, a2 = 0.f;
    #pragma unroll
    for (int i = tid; i < Dd; i += 256) { float v = xr[i]; a += v; a2 += v * v; }
    s1[tid] = a; s2[tid] = a2; __syncthreads();
    for (int s = 128; s > 0; s >>= 1) {
        if (tid < s) { s1[tid] += s1[tid + s]; s2[tid] += s2[tid + s]; }
        __syncthreads();
    }
    float mean = s1[0] * (1.f / Dd);
    float var  = s2[0] * (1.f / Dd) - mean * mean;
    float rstd = rsqrtf(var + EPSf);
    float* orow = out + (size_t)row * Dd;
    for (int i = tid; i < Dd; i += 256)
        orow[i] = (xr[i] - mean) * rstd * g[i] + b[i];
}

// ---------------- generic 128x128x8 SGEMM (M,N,K multiples of 128/128/8) ----
// C = A@B (+bias) (+residual) (relu?)
__global__ __launch_bounds__(256)
void gemm128_kernel(const float* __restrict__ A, const float* __restrict__ B,
                    float* __restrict__ C,
                    int M, int N, int K, int lda, int ldb, int ldc,
                    const float* __restrict__ bias,
                    const float* __restrict__ residual, int ldr,
                    int relu) {
    __shared__ float As[8][128];
    __shared__ float Bs[8][128];
    int tid = threadIdx.x;
    int tx = tid & 15, ty = tid >> 4;
    int n0 = blockIdx.x * 128, m0 = blockIdx.y * 128;
    float acc[8][8];
    #pragma unroll
    for (int i = 0; i < 8; i++)
        #pragma unroll
        for (int j = 0; j < 8; j++) acc[i][j] = 0.f;

    int ar = tid >> 1, ac = (tid & 1) * 4;     // A loader: 128 rows x 8 cols
    int br = tid >> 5, bc = (tid & 31) * 4;    // B loader: 8 rows x 128 cols
    const float* Aptr = A + (size_t)(m0 + ar) * lda + ac;
    const float* Bptr = B + (size_t)br * ldb + n0 + bc;

    for (int kk = 0; kk < K; kk += 8) {
        float4 av = *(const float4*)(Aptr + kk);
        float4 bv = *(const float4*)(Bptr + (size_t)kk * ldb);
        __syncthreads();
        As[ac + 0][ar] = av.x; As[ac + 1][ar] = av.y;
        As[ac + 2][ar] = av.z; As[ac + 3][ar] = av.w;
        *(float4*)&Bs[br][bc] = bv;
        __syncthreads();
        #pragma unroll
        for (int k = 0; k < 8; ++k) {
            float a[8], b[8];
            *(float4*)(a)     = *(const float4*)&As[k][ty * 8];
            *(float4*)(a + 4) = *(const float4*)&As[k][ty * 8 + 4];
            *(float4*)(b)     = *(const float4*)&Bs[k][tx * 8];
            *(float4*)(b + 4) = *(const float4*)&Bs[k][tx * 8 + 4];
            #pragma unroll
            for (int i = 0; i < 8; i++)
                #pragma unroll
                for (int j = 0; j < 8; j++) acc[i][j] = fmaf(a[i], b[j], acc[i][j]);
        }
    }
    #pragma unroll
    for (int i = 0; i < 8; i++) {
        int m = m0 + ty * 8 + i;
        #pragma unroll
        for (int j = 0; j < 8; j++) {
            int n = n0 + tx * 8 + j;
            float v = acc[i][j];
            if (bias) v += bias[n];
            if (residual) v += residual[(size_t)m * ldr + n];
            if (relu) v = fmaxf(v, 0.f);
            C[(size_t)m * ldc + n] = v;
        }
    }
}

// ---------------- 64x64 tile GEMM (N==64, one tile wide), BK=16 -------------
// A loads are SCALAR (A may be 4-byte-aligned only: attn buffer = d_out+1).
__device__ __forceinline__ void gemm64_tile(const float* __restrict__ A, int lda,
                                            const float* __restrict__ B, int ldb,
                                            float* __restrict__ C, int ldc, int K) {
    __shared__ float As[16][64];
    __shared__ float Bs[16][64];
    int tid = threadIdx.x;
    int tx = tid & 15, ty = tid >> 4;
    float acc[4][4];
    #pragma unroll
    for (int i = 0; i < 4; i++)
        #pragma unroll
        for (int j = 0; j < 4; j++) acc[i][j] = 0.f;

    int ar = tid >> 2, ac = (tid & 3) * 4;     // A: 64 rows x 16 cols
    int br = tid >> 4, bc = (tid & 15) * 4;    // B: 16 rows x 64 cols
    const float* Ap = A + (size_t)ar * lda;

    for (int kk = 0; kk < K; kk += 16) {
        float a0 = Ap[kk + ac + 0];
        float a1 = Ap[kk + ac + 1];
        float a2 = Ap[kk + ac + 2];
        float a3 = Ap[kk + ac + 3];
        float4 bv = *(const float4*)(B + (size_t)(kk + br) * ldb + bc);
        __syncthreads();
        As[ac + 0][ar] = a0; As[ac + 1][ar] = a1;
        As[ac + 2][ar] = a2; As[ac + 3][ar] = a3;
        *(float4*)&Bs[br][bc] = bv;
        __syncthreads();
        #pragma unroll
        for (int k = 0; k < 16; ++k) {
            float4 a = *(const float4*)&As[k][ty * 4];
            float4 b = *(const float4*)&Bs[k][tx * 4];
            acc[0][0] = fmaf(a.x, b.x, acc[0][0]); acc[0][1] = fmaf(a.x, b.y, acc[0][1]);
            acc[0][2] = fmaf(a.x, b.z, acc[0][2]); acc[0][3] = fmaf(a.x, b.w, acc[0][3]);
            acc[1][0] = fmaf(a.y, b.x, acc[1][0]); acc[1][1] = fmaf(a.y, b.y, acc[1][1]);
            acc[1][2] = fmaf(a.y, b.z, acc[1][2]); acc[1][3] = fmaf(a.y, b.w, acc[1][3]);
            acc[2][0] = fmaf(a.z, b.x, acc[2][0]); acc[2][1] = fmaf(a.z, b.y, acc[2][1]);
            acc[2][2] = fmaf(a.z, b.z, acc[2][2]); acc[2][3] = fmaf(a.z, b.w, acc[2][3]);
            acc[3][0] = fmaf(a.w, b.x, acc[3][0]); acc[3][1] = fmaf(a.w, b.y, acc[3][1]);
            acc[3][2] = fmaf(a.w, b.z, acc[3][2]); acc[3][3] = fmaf(a.w, b.w, acc[3][3]);
        }
    }
    #pragma unroll
    for (int i = 0; i < 4; i++)
        #pragma unroll
        for (int j = 0; j < 4; j++)
            C[(size_t)(ty * 4 + i) * ldc + tx * 4 + j] = acc[i][j];
}

// ---------------- QKV: per (mat, head) 4096x64 = h @ W ----------------------
__global__ __launch_bounds__(256)
void qkv_kernel(const float* __restrict__ Wq, const float* __restrict__ Wk,
                const float* __restrict__ Wv, int l) {
    int z = blockIdx.z;
    int mat = z / Hh, hd = z % Hh;
    const float* W = (mat == 0 ? Wq : (mat == 1 ? Wk : Wv)) +
                     ((size_t)l * Hh + hd) * Dd * HSs;
    float* out = (mat == 0 ? g_q : (mat == 1 ? g_k : g_v)) + hd * HSs;
    size_t m0 = (size_t)blockIdx.y * 64;
    gemm64_tile(g_h + m0 * Dd, Dd, W, HSs, out + m0 * Dd, Dd, Dd);
}

// ---------------- scores = q @ k^T * scale (lower-triangular tiles) ---------
__global__ __launch_bounds__(256)
void scores_kernel(float* __restrict__ attnL) {
    int tj = blockIdx.x, ti = blockIdx.y;
    if (tj > ti) return;
    int z = blockIdx.z;
    int b = z >> 4, hd = z & 15;
    const float* qp = g_q + (size_t)b * Tt * Dd + hd * HSs + (size_t)ti * 64 * Dd;
    const float* kp = g_k + (size_t)b * Tt * Dd + hd * HSs + (size_t)tj * 64 * Dd;
    __shared__ float Qs[64][64];
    __shared__ float Ks[64][64];
    int tid = threadIdx.x;
    int r = tid >> 2, c0 = (tid & 3) * 16;
    #pragma unroll
    for (int u = 0; u < 4; ++u) {
        float4 qv = *(const float4*)(qp + (size_t)r * Dd + c0 + u * 4);
        float4 kv = *(const float4*)(kp + (size_t)r * Dd + c0 + u * 4);
        int c = c0 + u * 4;
        Qs[c + 0][r] = qv.x; Qs[c + 1][r] = qv.y; Qs[c + 2][r] = qv.z; Qs[c + 3][r] = qv.w;
        Ks[c + 0][r] = kv.x; Ks[c + 1][r] = kv.y; Ks[c + 2][r] = kv.z; Ks[c + 3][r] = kv.w;
    }
    __syncthreads();
    int tx = tid & 15, ty = tid >> 4;
    float acc[4][4];
    #pragma unroll
    for (int i = 0; i < 4; i++)
        #pragma unroll
        for (int j = 0; j < 4; j++) acc[i][j] = 0.f;
    #pragma unroll
    for (int s = 0; s < 64; ++s) {
        float4 a = *(const float4*)&Qs[s][ty * 4];
        float4 b2 = *(const float4*)&Ks[s][tx * 4];
        acc[0][0] = fmaf(a.x, b2.x, acc[0][0]); acc[0][1] = fmaf(a.x, b2.y, acc[0][1]);
        acc[0][2] = fmaf(a.x, b2.z, acc[0][2]); acc[0][3] = fmaf(a.x, b2.w, acc[0][3]);
        acc[1][0] = fmaf(a.y, b2.x, acc[1][0]); acc[1][1] = fmaf(a.y, b2.y, acc[1][1]);
        acc[1][2] = fmaf(a.y, b2.z, acc[1][2]); acc[1][3] = fmaf(a.y, b2.w, acc[1][3]);
        acc[2][0] = fmaf(a.z, b2.x, acc[2][0]); acc[2][1] = fmaf(a.z, b2.y, acc[2][1]);
        acc[2][2] = fmaf(a.z, b2.z, acc[2][2]); acc[2][3] = fmaf(a.z, b2.w, acc[2][3]);
        acc[3][0] = fmaf(a.w, b2.x, acc[3][0]); acc[3][1] = fmaf(a.w, b2.y, acc[3][1]);
        acc[3][2] = fmaf(a.w, b2.z, acc[3][2]); acc[3][3] = fmaf(a.w, b2.w, acc[3][3]);
    }
    float* cp = attnL + (size_t)z * Tt * Tt + (size_t)(ti * 64) * Tt + tj * 64;
    const float scale = 0.125f;  // HS^-0.5
    #pragma unroll
    for (int i = 0; i < 4; i++)
        #pragma unroll
        for (int j = 0; j < 4; j++)
            cp[(size_t)(ty * 4 + i) * Tt + tx * 4 + j] = acc[i][j] * scale;
}

// ---------------- causal softmax, in-place on the attn output slice ---------
__global__ void softmax_kernel(float* __restrict__ attnL) {
    __shared__ float sd[256];
    int rgl = blockIdx.x;             // 0..B*H*T-1
    int bh = rgl >> 10, t = rgl & (Tt - 1);
    float* p = attnL + (size_t)bh * Tt * Tt + (size_t)t * Tt;
    int n = t + 1;
    int tid = threadIdx.x;
    float mx = -3.4e38f;
    for (int i = tid; i < n; i += 256) mx = fmaxf(mx, p[i]);
    sd[tid] = mx; __syncthreads();
    for (int s = 128; s > 0; s >>= 1) {
        if (tid < s) sd[tid] = fmaxf(sd[tid], sd[tid + s]);
        __syncthreads();
    }
    mx = sd[0]; __syncthreads();
    float sum = 0.f;
    for (int i = tid; i < n; i += 256) sum += __expf(p[i] - mx);
    sd[tid] = sum; __syncthreads();
    for (int s = 128; s > 0; s >>= 1) {
        if (tid < s) sd[tid] += sd[tid + s];
        __syncthreads();
    }
    float inv = 1.f / sd[0];
    for (int i = tid; i < Tt; i += 256)
        p[i] = (i < n) ? __expf(p[i] - mx) * inv : 0.f;
}

// ---------------- o = wei @ v  (per b,h slice) ------------------------------
__global__ __launch_bounds__(256)
void attnv_kernel(const float* __restrict__ attnL) {
    int z = blockIdx.z;
    int b = z >> 4, hd = z & 15;
    const float* A = attnL + (size_t)z * Tt * Tt + (size_t)blockIdx.y * 64 * Tt;
    const float* B = g_v + (size_t)b * Tt * Dd + hd * HSs;
    float* C = g_o + (size_t)b * Tt * Dd + hd * HSs + (size_t)blockIdx.y * 64 * Dd;
    gemm64_tile(A, Tt, B, Dd, C, Dd, Tt);
}

// ---------------- fused log-softmax NLL per row -----------------------------
__global__ void loss_row_kernel(const int* __restrict__ targets) {
    __shared__ float sd[256];
    int r = blockIdx.x;
    const float* p = g_logits + (size_t)r * Vv;
    int tid = threadIdx.x;
    float mx = -3.4e38f;
    for (int i = tid; i < Vv; i += 256) mx = fmaxf(mx, p[i]);
    sd[tid] = mx; __syncthreads();
    for (int s = 128; s > 0; s >>= 1) {
        if (tid < s) sd[tid] = fmaxf(sd[tid], sd[tid + s]);
        __syncthreads();
    }
    mx = sd[0]; __syncthreads();
    float sum = 0.f;
    for (int i = tid; i < Vv; i += 256) sum += __expf(p[i] - mx);
    sd[tid] = sum; __syncthreads();
    for (int s = 128; s > 0; s >>= 1) {
        if (tid < s) sd[tid] += sd[tid + s];
        __syncthreads();
    }
    if (tid == 0)
        g_rownll[r] = logf(sd[0]) + mx - p[targets[r]];
}

__global__ void loss_final_kernel(float* __restrict__ out) {
    __shared__ float sd[256];
    int tid = threadIdx.x;
    float s = 0.f;
    for (int i = tid; i < BT; i += 256) s += g_rownll[i];
    sd[tid] = s; __syncthreads();
    for (int st = 128; st > 0; st >>= 1) {
        if (tid < st) sd[tid] += sd[tid + st];
        __syncthreads();
    }
    if (tid == 0) out[0] = sd[0] * (1.f / BT);
}

// ---------------- host orchestration ----------------------------------------
extern "C" void kernel_launch(void* const* d_in, const int* in_sizes, int n_in,
                              void* d_out, int out_size) {
    (void)in_sizes; (void)n_in; (void)out_size;
    const int*   idx     = (const int*)d_in[0];
    const int*   targets = (const int*)d_in[1];
    const float* tok     = (const float*)d_in[2];
    const float* pos     = (const float*)d_in[3];
    const float* ln1_g   = (const float*)d_in[4];
    const float* ln1_b   = (const float*)d_in[5];
    const float* Wq      = (const float*)d_in[6];
    const float* Wk      = (const float*)d_in[7];
    const float* Wv      = (const float*)d_in[8];
    const float* Wp      = (const float*)d_in[9];
    const float* bp      = (const float*)d_in[10];
    const float* ln2_g   = (const float*)d_in[11];
    const float* ln2_b   = (const float*)d_in[12];
    const float* W1      = (const float*)d_in[13];
    const float* b1      = (const float*)d_in[14];
    const float* W2      = (const float*)d_in[15];
    const float* b2      = (const float*)d_in[16];
    const float* lnf_g   = (const float*)d_in[17];
    const float* lnf_b   = (const float*)d_in[18];
    const float* Wlm     = (const float*)d_in[19];
    const float* blm     = (const float*)d_in[20];

    float* out  = (float*)d_out;
    float* attn = out + 1;   // [L,B,H,T,T], 4-byte aligned only

    float *px, *ph, *po, *pff, *plog;
    cudaGetSymbolAddress((void**)&px,   g_x);
    cudaGetSymbolAddress((void**)&ph,   g_h);
    cudaGetSymbolAddress((void**)&po,   g_o);
    cudaGetSymbolAddress((void**)&pff,  g_ff);
    cudaGetSymbolAddress((void**)&plog, g_logits);

    embed_kernel<<<BT * Dd / 256, 256>>>(idx, tok, pos);

    for (int l = 0; l < Ll; ++l) {
        float* attnL = attn + (size_t)l * Bb * Hh * Tt * Tt;

        ln_kernel<<<BT, 256>>>(px, ln1_g + (size_t)l * Dd, ln1_b + (size_t)l * Dd, ph);

        dim3 gq(1, BT / 64, 3 * Hh);
        qkv_kernel<<<gq, 256>>>(Wq, Wk, Wv, l);

        dim3 gs(Tt / 64, Tt / 64, Bb * Hh);
        scores_kernel<<<gs, 256>>>(attnL);

        softmax_kernel<<<Bb * Hh * Tt, 256>>>(attnL);

        dim3 ga(1, Tt / 64, Bb * Hh);
        attnv_kernel<<<ga, 256>>>(attnL);

        dim3 gp(Dd / 128, BT / 128);
        gemm128_kernel<<<gp, 256>>>(po, Wp + (size_t)l * Dd * Dd, px,
                                    BT, Dd, Dd, Dd, Dd, Dd,
                                    bp + (size_t)l * Dd, px, Dd, 0);

        ln_kernel<<<BT, 256>>>(px, ln2_g + (size_t)l * Dd, ln2_b + (size_t)l * Dd, ph);

        dim3 g1(FFf / 128, BT / 128);
        gemm128_kernel<<<g1, 256>>>(ph, W1 + (size_t)l * Dd * FFf, pff,
                                    BT, FFf, Dd, Dd, FFf, FFf,
                                    b1 + (size_t)l * FFf, nullptr, 0, 1);

        dim3 g2(Dd / 128, BT / 128);
        gemm128_kernel<<<g2, 256>>>(pff, W2 + (size_t)l * FFf * Dd, px,
                                    BT, Dd, FFf, FFf, Dd, Dd,
                                    b2 + (size_t)l * Dd, px, Dd, 0);
    }

    ln_kernel<<<BT, 256>>>(px, lnf_g, lnf_b, ph);

    dim3 gl(Vv / 128, BT / 128);
    gemm128_kernel<<<gl, 256>>>(ph, Wlm, plog,
                                BT, Vv, Dd, Dd, Vv, Vv,
                                blm, nullptr, 0, 0);

    loss_row_kernel<<<BT, 256>>>(targets);
    loss_final_kernel<<<1, 256>>>(out);
}

// round 2
// speedup vs baseline: 1.0020x; 1.0020x over previous
#include <cuda_runtime.h>
#include <math.h>
#include <stdint.h>

// Problem constants
#define Bb   4
#define Tt   1024
#define Dd   1024
#define Hh   16
#define HSs  64
#define Ll   4
#define FFf  4096
#define Vv   32000
#define BT   (Bb*Tt)          // 4096
#define EPSf 1e-5f

// ---------------- scratch (device globals; no allocs allowed) ----------------
__device__ float g_x[BT*Dd];
__device__ float g_h[BT*Dd];
__device__ float g_q[BT*Dd];
__device__ float g_k[BT*Dd];
__device__ float g_v[BT*Dd];
__device__ float g_o[BT*Dd];
__device__ float g_ff[(size_t)BT*FFf];
__device__ float g_logits[(size_t)BT*Vv];
__device__ float g_rownll[BT];

// ---------------- embed: x = tok_emb[idx] + pos_emb ----------------
__global__ void embed_kernel(const int* __restrict__ idx,
                             const float* __restrict__ tok,
                             const float* __restrict__ pos) {
    size_t i = (size_t)blockIdx.x * 256 + threadIdx.x;   // BT*Dd total
    int d  = (int)(i & (Dd - 1));
    int bt = (int)(i >> 10);
    int t  = bt & (Tt - 1);
    g_x[i] = tok[(size_t)idx[bt] * Dd + d] + pos[(size_t)t * Dd + d];
}

// ---------------- layernorm: one block per row ----------------
__global__ void ln_kernel(const float* __restrict__ x,
                          const float* __restrict__ g,
                          const float* __restrict__ b,
                          float* __restrict__ out) {
    __shared__ float s1[256], s2[256];
    int row = blockIdx.x;
    const float* xr = x + (size_t)row * Dd;
    int tid = threadIdx.x;
    float a = 0.f, a2 = 0.f;
    #pragma unroll
    for (int i = tid; i < Dd; i += 256) { float v = xr[i]; a += v; a2 += v * v; }
    s1[tid] = a; s2[tid] = a2; __syncthreads();
    for (int s = 128; s > 0; s >>= 1) {
        if (tid < s) { s1[tid] += s1[tid + s]; s2[tid] += s2[tid + s]; }
        __syncthreads();
    }
    float mean = s1[0] * (1.f / Dd);
    float var  = s2[0] * (1.f / Dd) - mean * mean;
    float rstd = rsqrtf(var + EPSf);
    float* orow = out + (size_t)row * Dd;
    for (int i = tid; i < Dd; i += 256)
        orow[i] = (xr[i] - mean) * rstd * g[i] + b[i];
}

// ---------------- generic 128x128x8 SGEMM (M,N,K multiples of 128/128/8) ----
// C = A@B (+bias) (+residual) (relu?)
__global__ __launch_bounds__(256)
void gemm128_kernel(const float* __restrict__ A, const float* __restrict__ B,
                    float* __restrict__ C,
                    int M, int N, int K, int lda, int ldb, int ldc,
                    const float* __restrict__ bias,
                    const float* __restrict__ residual, int ldr,
                    int relu) {
    __shared__ float As[8][128];
    __shared__ float Bs[8][128];
    int tid = threadIdx.x;
    int tx = tid & 15, ty = tid >> 4;
    int n0 = blockIdx.x * 128, m0 = blockIdx.y * 128;
    float acc[8][8];
    #pragma unroll
    for (int i = 0; i < 8; i++)
        #pragma unroll
        for (int j = 0; j < 8; j++) acc[i][j] = 0.f;

    int ar = tid >> 1, ac = (tid & 1) * 4;     // A loader: 128 rows x 8 cols
    int br = tid >> 5, bc = (tid & 31) * 4;    // B loader: 8 rows x 128 cols
    const float* Aptr = A + (size_t)(m0 + ar) * lda + ac;
    const float* Bptr = B + (size_t)br * ldb + n0 + bc;

    for (int kk = 0; kk < K; kk += 8) {
        float4 av = *(const float4*)(Aptr + kk);
        float4 bv = *(const float4*)(Bptr + (size_t)kk * ldb);
        __syncthreads();
        As[ac + 0][ar] = av.x; As[ac + 1][ar] = av.y;
        As[ac + 2][ar] = av.z; As[ac + 3][ar] = av.w;
        *(float4*)&Bs[br][bc] = bv;
        __syncthreads();
        #pragma unroll
        for (int k = 0; k < 8; ++k) {
            float a[8], b[8];
            *(float4*)(a)     = *(const float4*)&As[k][ty * 8];
            *(float4*)(a + 4) = *(const float4*)&As[k][ty * 8 + 4];
            *(float4*)(b)     = *(const float4*)&Bs[k][tx * 8];
            *(float4*)(b + 4) = *(const float4*)&Bs[k][tx * 8 + 4];
            #pragma unroll
            for (int i = 0; i < 8; i++)
                #pragma unroll
                for (int j = 0; j < 8; j++) acc[i][j] = fmaf(a[i], b[j], acc[i][j]);
        }
    }
    #pragma unroll
    for (int i = 0; i < 8; i++) {
        int m = m0 + ty * 8 + i;
        #pragma unroll
        for (int j = 0; j < 8; j++) {
            int n = n0 + tx * 8 + j;
            float v = acc[i][j];
            if (bias) v += bias[n];
            if (residual) v += residual[(size_t)m * ldr + n];
            if (relu) v = fmaxf(v, 0.f);
            C[(size_t)m * ldc + n] = v;
        }
    }
}

// ---------------- 64x64 tile GEMM (N==64, one tile wide), BK=16 -------------
// A loads are SCALAR (A may be 4-byte-aligned only: attn buffer = d_out+1).
__device__ __forceinline__ void gemm64_tile(const float* __restrict__ A, int lda,
                                            const float* __restrict__ B, int ldb,
                                            float* __restrict__ C, int ldc, int K) {
    __shared__ float As[16][64];
    __shared__ float Bs[16][64];
    int tid = threadIdx.x;
    int tx = tid & 15, ty = tid >> 4;
    float acc[4][4];
    #pragma unroll
    for (int i = 0; i < 4; i++)
        #pragma unroll
        for (int j = 0; j < 4; j++) acc[i][j] = 0.f;

    int ar = tid >> 2, ac = (tid & 3) * 4;     // A: 64 rows x 16 cols
    int br = tid >> 4, bc = (tid & 15) * 4;    // B: 16 rows x 64 cols
    const float* Ap = A + (size_t)ar * lda;

    for (int kk = 0; kk < K; kk += 16) {
        float a0 = Ap[kk + ac + 0];
        float a1 = Ap[kk + ac + 1];
        float a2 = Ap[kk + ac + 2];
        float a3 = Ap[kk + ac + 3];
        float4 bv = *(const float4*)(B + (size_t)(kk + br) * ldb + bc);
        __syncthreads();
        As[ac + 0][ar] = a0; As[ac + 1][ar] = a1;
        As[ac + 2][ar] = a2; As[ac + 3][ar] = a3;
        *(float4*)&Bs[br][bc] = bv;
        __syncthreads();
        #pragma unroll
        for (int k = 0; k < 16; ++k) {
            float4 a = *(const float4*)&As[k][ty * 4];
            float4 b = *(const float4*)&Bs[k][tx * 4];
            acc[0][0] = fmaf(a.x, b.x, acc[0][0]); acc[0][1] = fmaf(a.x, b.y, acc[0][1]);
            acc[0][2] = fmaf(a.x, b.z, acc[0][2]); acc[0][3] = fmaf(a.x, b.w, acc[0][3]);
            acc[1][0] = fmaf(a.y, b.x, acc[1][0]); acc[1][1] = fmaf(a.y, b.y, acc[1][1]);
            acc[1][2] = fmaf(a.y, b.z, acc[1][2]); acc[1][3] = fmaf(a.y, b.w, acc[1][3]);
            acc[2][0] = fmaf(a.z, b.x, acc[2][0]); acc[2][1] = fmaf(a.z, b.y, acc[2][1]);
            acc[2][2] = fmaf(a.z, b.z, acc[2][2]); acc[2][3] = fmaf(a.z, b.w, acc[2][3]);
            acc[3][0] = fmaf(a.w, b.x, acc[3][0]); acc[3][1] = fmaf(a.w, b.y, acc[3][1]);
            acc[3][2] = fmaf(a.w, b.z, acc[3][2]); acc[3][3] = fmaf(a.w, b.w, acc[3][3]);
        }
    }
    #pragma unroll
    for (int i = 0; i < 4; i++)
        #pragma unroll
        for (int j = 0; j < 4; j++)
            C[(size_t)(ty * 4 + i) * ldc + tx * 4 + j] = acc[i][j];
}

// ---------------- QKV: per (mat, head) 4096x64 = h @ W ----------------------
__global__ __launch_bounds__(256)
void qkv_kernel(const float* __restrict__ Wq, const float* __restrict__ Wk,
                const float* __restrict__ Wv, int l) {
    int z = blockIdx.z;
    int mat = z / Hh, hd = z % Hh;
    const float* W = (mat == 0 ? Wq : (mat == 1 ? Wk : Wv)) +
                     ((size_t)l * Hh + hd) * Dd * HSs;
    float* out = (mat == 0 ? g_q : (mat == 1 ? g_k : g_v)) + hd * HSs;
    size_t m0 = (size_t)blockIdx.y * 64;
    gemm64_tile(g_h + m0 * Dd, Dd, W, HSs, out + m0 * Dd, Dd, Dd);
}

// ---------------- scores = q @ k^T * scale (lower-triangular tiles) ---------
__global__ __launch_bounds__(256)
void scores_kernel(float* __restrict__ attnL) {
    int tj = blockIdx.x, ti = blockIdx.y;
    if (tj > ti) return;
    int z = blockIdx.z;
    int b = z >> 4, hd = z & 15;
    const float* qp = g_q + (size_t)b * Tt * Dd + hd * HSs + (size_t)ti * 64 * Dd;
    const float* kp = g_k + (size_t)b * Tt * Dd + hd * HSs + (size_t)tj * 64 * Dd;
    __shared__ float Qs[64][64];
    __shared__ float Ks[64][64];
    int tid = threadIdx.x;
    int r = tid >> 2, c0 = (tid & 3) * 16;
    #pragma unroll
    for (int u = 0; u < 4; ++u) {
        float4 qv = *(const float4*)(qp + (size_t)r * Dd + c0 + u * 4);
        float4 kv = *(const float4*)(kp + (size_t)r * Dd + c0 + u * 4);
        int c = c0 + u * 4;
        Qs[c + 0][r] = qv.x; Qs[c + 1][r] = qv.y; Qs[c + 2][r] = qv.z; Qs[c + 3][r] = qv.w;
        Ks[c + 0][r] = kv.x; Ks[c + 1][r] = kv.y; Ks[c + 2][r] = kv.z; Ks[c + 3][r] = kv.w;
    }
    __syncthreads();
    int tx = tid & 15, ty = tid >> 4;
    float acc[4][4];
    #pragma unroll
    for (int i = 0; i < 4; i++)
        #pragma unroll
        for (int j = 0; j < 4; j++) acc[i][j] = 0.f;
    #pragma unroll
    for (int s = 0; s < 64; ++s) {
        float4 a = *(const float4*)&Qs[s][ty * 4];
        float4 b2 = *(const float4*)&Ks[s][tx * 4];
        acc[0][0] = fmaf(a.x, b2.x, acc[0][0]); acc[0][1] = fmaf(a.x, b2.y, acc[0][1]);
        acc[0][2] = fmaf(a.x, b2.z, acc[0][2]); acc[0][3] = fmaf(a.x, b2.w, acc[0][3]);
        acc[1][0] = fmaf(a.y, b2.x, acc[1][0]); acc[1][1] = fmaf(a.y, b2.y, acc[1][1]);
        acc[1][2] = fmaf(a.y, b2.z, acc[1][2]); acc[1][3] = fmaf(a.y, b2.w, acc[1][3]);
        acc[2][0] = fmaf(a.z, b2.x, acc[2][0]); acc[2][1] = fmaf(a.z, b2.y, acc[2][1]);
        acc[2][2] = fmaf(a.z, b2.z, acc[2][2]); acc[2][3] = fmaf(a.z, b2.w, acc[2][3]);
        acc[3][0] = fmaf(a.w, b2.x, acc[3][0]); acc[3][1] = fmaf(a.w, b2.y, acc[3][1]);
        acc[3][2] = fmaf(a.w, b2.z, acc[3][2]); acc[3][3] = fmaf(a.w, b2.w, acc[3][3]);
    }
    float* cp = attnL + (size_t)z * Tt * Tt + (size_t)(ti * 64) * Tt + tj * 64;
    const float scale = 0.125f;  // HS^-0.5
    #pragma unroll
    for (int i = 0; i < 4; i++)
        #pragma unroll
        for (int j = 0; j < 4; j++)
            cp[(size_t)(ty * 4 + i) * Tt + tx * 4 + j] = acc[i][j] * scale;
}

// ---------------- causal softmax, in-place on the attn output slice ---------
__global__ void softmax_kernel(float* __restrict__ attnL) {
    __shared__ float sd[256];
    int rgl = blockIdx.x;             // 0..B*H*T-1
    int bh = rgl >> 10, t = rgl & (Tt - 1);
    float* p = attnL + (size_t)bh * Tt * Tt + (size_t)t * Tt;
    int n = t + 1;
    int tid = threadIdx.x;
    float mx = -3.4e38f;
    for (int i = tid; i < n; i += 256) mx = fmaxf(mx, p[i]);
    sd[tid] = mx; __syncthreads();
    for (int s = 128; s > 0; s >>= 1) {
        if (tid < s) sd[tid] = fmaxf(sd[tid], sd[tid + s]);
        __syncthreads();
    }
    mx = sd[0]; __syncthreads();
    float sum = 0.f;
    for (int i = tid; i < n; i += 256) sum += __expf(p[i] - mx);
    sd[tid] = sum; __syncthreads();
    for (int s = 128; s > 0; s >>= 1) {
        if (tid < s) sd[tid] += sd[tid + s];
        __syncthreads();
    }
    float inv = 1.f / sd[0];
    for (int i = tid; i < Tt; i += 256)
        p[i] = (i < n) ? __expf(p[i] - mx) * inv : 0.f;
}

// ---------------- o = wei @ v  (per b,h slice) ------------------------------
__global__ __launch_bounds__(256)
void attnv_kernel(const float* __restrict__ attnL) {
    int z = blockIdx.z;
    int b = z >> 4, hd = z & 15;
    const float* A = attnL + (size_t)z * Tt * Tt + (size_t)blockIdx.y * 64 * Tt;
    const float* B = g_v + (size_t)b * Tt * Dd + hd * HSs;
    float* C = g_o + (size_t)b * Tt * Dd + hd * HSs + (size_t)blockIdx.y * 64 * Dd;
    gemm64_tile(A, Tt, B, Dd, C, Dd, Tt);
}

// ---------------- fused log-softmax NLL per row -----------------------------
__global__ void loss_row_kernel(const int* __restrict__ targets) {
    __shared__ float sd[256];
    int r = blockIdx.x;
    const float* p = g_logits + (size_t)r * Vv;
    int tid = threadIdx.x;
    float mx = -3.4e38f;
    for (int i = tid; i < Vv; i += 256) mx = fmaxf(mx, p[i]);
    sd[tid] = mx; __syncthreads();
    for (int s = 128; s > 0; s >>= 1) {
        if (tid < s) sd[tid] = fmaxf(sd[tid], sd[tid + s]);
        __syncthreads();
    }
    mx = sd[0]; __syncthreads();
    float sum = 0.f;
    for (int i = tid; i < Vv; i += 256) sum += __expf(p[i] - mx);
    sd[tid] = sum; __syncthreads();
    for (int s = 128; s > 0; s >>= 1) {
        if (tid < s) sd[tid] += sd[tid + s];
        __syncthreads();
    }
    if (tid == 0)
        g_rownll[r] = logf(sd[0]) + mx - p[targets[r]];
}

__global__ void loss_final_kernel(float* __restrict__ out) {
    __shared__ float sd[256];
    int tid = threadIdx.x;
    float s = 0.f;
    for (int i = tid; i < BT; i += 256) s += g_rownll[i];
    sd[tid] = s; __syncthreads();
    for (int st = 128; st > 0; st >>= 1) {
        if (tid < st) sd[tid] += sd[tid + st];
        __syncthreads();
    }
    if (tid == 0) out[0] = sd[0] * (1.f / BT);
}

// ---------------- host orchestration ----------------------------------------
extern "C" void kernel_launch(void* const* d_in, const int* in_sizes, int n_in,
                              void* d_out, int out_size) {
    (void)in_sizes; (void)n_in; (void)out_size;
    const int*   idx     = (const int*)d_in[0];
    const int*   targets = (const int*)d_in[1];
    const float* tok     = (const float*)d_in[2];
    const float* pos     = (const float*)d_in[3];
    const float* ln1_g   = (const float*)d_in[4];
    const float* ln1_b   = (const float*)d_in[5];
    const float* Wq      = (const float*)d_in[6];
    const float* Wk      = (const float*)d_in[7];
    const float* Wv      = (const float*)d_in[8];
    const float* Wp      = (const float*)d_in[9];
    const float* bp      = (const float*)d_in[10];
    const float* ln2_g   = (const float*)d_in[11];
    const float* ln2_b   = (const float*)d_in[12];
    const float* W1      = (const float*)d_in[13];
    const float* b1      = (const float*)d_in[14];
    const float* W2      = (const float*)d_in[15];
    const float* b2      = (const float*)d_in[16];
    const float* lnf_g   = (const float*)d_in[17];
    const float* lnf_b   = (const float*)d_in[18];
    const float* Wlm     = (const float*)d_in[19];
    const float* blm     = (const float*)d_in[20];

    float* out  = (float*)d_out;
    float* attn = out + 1;   // [L,B,H,T,T], 4-byte aligned only

    float *px, *ph, *po, *pff, *plog;
    cudaGetSymbolAddress((void**)&px,   g_x);
    cudaGetSymbolAddress((void**)&ph,   g_h);
    cudaGetSymbolAddress((void**)&po,   g_o);
    cudaGetSymbolAddress((void**)&pff,  g_ff);
    cudaGetSymbolAddress((void**)&plog, g_logits);

    embed_kernel<<<BT * Dd / 256, 256>>>(idx, tok, pos);

    for (int l = 0; l < Ll; ++l) {
        float* attnL = attn + (size_t)l * Bb * Hh * Tt * Tt;

        ln_kernel<<<BT, 256>>>(px, ln1_g + (size_t)l * Dd, ln1_b + (size_t)l * Dd, ph);

        dim3 gq(1, BT / 64, 3 * Hh);
        qkv_kernel<<<gq, 256>>>(Wq, Wk, Wv, l);

        dim3 gs(Tt / 64, Tt / 64, Bb * Hh);
        scores_kernel<<<gs, 256>>>(attnL);

        softmax_kernel<<<Bb * Hh * Tt, 256>>>(attnL);

        dim3 ga(1, Tt / 64, Bb * Hh);
        attnv_kernel<<<ga, 256>>>(attnL);

        dim3 gp(Dd / 128, BT / 128);
        gemm128_kernel<<<gp, 256>>>(po, Wp + (size_t)l * Dd * Dd, px,
                                    BT, Dd, Dd, Dd, Dd, Dd,
                                    bp + (size_t)l * Dd, px, Dd, 0);

        ln_kernel<<<BT, 256>>>(px, ln2_g + (size_t)l * Dd, ln2_b + (size_t)l * Dd, ph);

        dim3 g1(FFf / 128, BT / 128);
        gemm128_kernel<<<g1, 256>>>(ph, W1 + (size_t)l * Dd * FFf, pff,
                                    BT, FFf, Dd, Dd, FFf, FFf,
                                    b1 + (size_t)l * FFf, nullptr, 0, 1);

        dim3 g2(Dd / 128, BT / 128);
        gemm128_kernel<<<g2, 256>>>(pff, W2 + (size_t)l * FFf * Dd, px,
                                    BT, Dd, FFf, FFf, Dd, Dd,
                                    b2 + (size_t)l * Dd, px, Dd, 0);
    }

    ln_kernel<<<BT, 256>>>(px, lnf_g, lnf_b, ph);

    dim3 gl(Vv / 128, BT / 128);
    gemm128_kernel<<<gl, 256>>>(ph, Wlm, plog,
                                BT, Vv, Dd, Dd, Vv, Vv,
                                blm, nullptr, 0, 0);

    loss_row_kernel<<<BT, 256>>>(targets);
    loss_final_kernel<<<1, 256>>>(out);
}

// round 6
// speedup vs baseline: 2.0432x; 2.0390x over previous
#include <cuda_runtime.h>
#include <cuda_bf16.h>
#include <math.h>
#include <stdint.h>

// Problem constants
#define Bb   4
#define Tt   1024
#define Dd   1024
#define Hh   16
#define HSs  64
#define Ll   4
#define FFf  4096
#define Vv   32000
#define BT   (Bb*Tt)          // 4096
#define EPSf 1e-5f

// ---------------- scratch (device globals; no allocs allowed) ----------------
__device__ float g_x[BT*Dd];
__device__ float g_h[BT*Dd];
__device__ float g_q[BT*Dd];
__device__ float g_k[BT*Dd];
__device__ float g_vT[Bb*Hh*HSs*Tt];          // [bh][s][t]
__device__ float g_o[BT*Dd];
__device__ float g_ff[(size_t)BT*FFf];
__device__ float g_logits[(size_t)BT*Vv];
__device__ float g_rownll[BT];
// pre-transposed + bf16-split weights [N][K]
__device__ __nv_bfloat16 g_wqT_h[Ll*Hh*HSs*Dd], g_wqT_l[Ll*Hh*HSs*Dd];
__device__ __nv_bfloat16 g_wkT_h[Ll*Hh*HSs*Dd], g_wkT_l[Ll*Hh*HSs*Dd];
__device__ __nv_bfloat16 g_wvT_h[Ll*Hh*HSs*Dd], g_wvT_l[Ll*Hh*HSs*Dd];
__device__ __nv_bfloat16 g_wpT_h[(size_t)Ll*Dd*Dd], g_wpT_l[(size_t)Ll*Dd*Dd];
__device__ __nv_bfloat16 g_w1T_h[(size_t)Ll*FFf*Dd], g_w1T_l[(size_t)Ll*FFf*Dd];
__device__ __nv_bfloat16 g_w2T_h[(size_t)Ll*Dd*FFf], g_w2T_l[(size_t)Ll*Dd*FFf];
__device__ __nv_bfloat16 g_wlmT_h[(size_t)Vv*Dd],    g_wlmT_l[(size_t)Vv*Dd];

// ---------------- helpers ----------------
__device__ __forceinline__ uint32_t smem_u32(const void* p) {
    uint32_t a;
    asm("{ .reg .u64 t; cvta.to.shared.u64 t, %1; cvt.u32.u64 %0, t; }" : "=r"(a) : "l"(p));
    return a;
}
__device__ __forceinline__ void ldsm4(uint32_t& r0, uint32_t& r1, uint32_t& r2,
                                      uint32_t& r3, uint32_t addr) {
    asm volatile("ldmatrix.sync.aligned.m8n8.x4.shared.b16 {%0,%1,%2,%3}, [%4];"
                 : "=r"(r0), "=r"(r1), "=r"(r2), "=r"(r3) : "r"(addr));
}
__device__ __forceinline__ void mma16816(float* c, const uint32_t* a, const uint32_t* b) {
    asm volatile(
        "mma.sync.aligned.m16n8k16.row.col.f32.bf16.bf16.f32 "
        "{%0,%1,%2,%3}, {%4,%5,%6,%7}, {%8,%9}, {%0,%1,%2,%3};"
        : "+f"(c[0]), "+f"(c[1]), "+f"(c[2]), "+f"(c[3])
        : "r"(a[0]), "r"(a[1]), "r"(a[2]), "r"(a[3]), "r"(b[0]), "r"(b[1]));
}
// split float pair -> bf16x2 hi and lo (packed u32)
__device__ __forceinline__ void split2(float x, float y, uint32_t& h, uint32_t& l) {
    __nv_bfloat162 h2 = __floats2bfloat162_rn(x, y);
    float2 hf = __bfloat1622float2(h2);
    __nv_bfloat162 l2 = __floats2bfloat162_rn(x - hf.x, y - hf.y);
    h = *reinterpret_cast<uint32_t*>(&h2);
    l = *reinterpret_cast<uint32_t*>(&l2);
}

// ---------------- weight transpose + bf16 hi/lo split -----------------------
// in: W[z][R][C] row-major; out: WT_hi/lo[z][C][R] bf16
__global__ void wsplit_kernel(const float* __restrict__ W,
                              __nv_bfloat16* __restrict__ Whi,
                              __nv_bfloat16* __restrict__ Wlo,
                              int R, int C) {
    __shared__ float ts[32][33];
    size_t mo = (size_t)blockIdx.z * R * C;
    int c0 = blockIdx.x * 32, r0 = blockIdx.y * 32;
    int tx = threadIdx.x, ty = threadIdx.y;
    #pragma unroll
    for (int i = 0; i < 4; ++i) {
        int r = r0 + ty + i * 8;
        ts[ty + i * 8][tx] = W[mo + (size_t)r * C + c0 + tx];
    }
    __syncthreads();
    #pragma unroll
    for (int i = 0; i < 4; ++i) {
        int n = c0 + ty + i * 8;
        int k = r0 + tx;
        float v = ts[tx][ty + i * 8];
        __nv_bfloat16 h = __float2bfloat16(v);
        __nv_bfloat16 l = __float2bfloat16(v - __bfloat162float(h));
        Whi[mo + (size_t)n * R + k] = h;
        Wlo[mo + (size_t)n * R + k] = l;
    }
}

// ---------------- unified bf16-split tensor-core GEMM -----------------------
// D[128 x BN] = A[m0.., K] (fp32) * B[n0.., K]^T, 3-product bf16 split.
// OMODE 0: C[m*ldc+n] (+bias)(+resid)(relu)
// OMODE 1: scores — C[m*ldc+n] = v*0.125, skip tiles with n0 > m0 (causal)
// OMODE 2: vT scatter — C[((m>>10)*16+(n>>6))*65536 + (n&63)*1024 + (m&1023)]
template<int BN, bool AVEC, bool BPRE, int OMODE>
__global__ __launch_bounds__(256)
void gmma_kernel(const float* __restrict__ A, const void* __restrict__ B1v,
                 const void* __restrict__ B2v, float* __restrict__ C,
                 const float* __restrict__ bias, const float* __restrict__ resid,
                 int relu, int K, int lda, int ldb, int ldc,
                 size_t aZh, size_t aZl, size_t bZh, size_t bZl,
                 size_t cZh, size_t cZl) {
    constexpr int STR = 80;                    // bytes per k-row (32 bf16 + 16B pad)
    constexpr int NT8 = BN / 32;               // n8 tiles per warp
    constexpr int NB16 = NT8 / 2;              // n16 ldmatrix groups per warp
    constexpr int NBS = BN / 32;               // B staging elems per thread
    __shared__ __align__(16) unsigned char smem[(256 + 2 * BN) * STR];
    const int SM_AH = 0, SM_AL = 128 * STR, SM_BH = 256 * STR;

    int m0 = blockIdx.x * 128, n0 = blockIdx.y * BN;
    if (OMODE == 1 && n0 > m0) return;
    int z = blockIdx.z;
    A += (size_t)(z >> 4) * aZh + (size_t)(z & 15) * aZl;
    const float* Bf = (const float*)B1v;
    const __nv_bfloat16* Bh16 = (const __nv_bfloat16*)B1v;
    const __nv_bfloat16* Bl16 = (const __nv_bfloat16*)B2v;
    if (BPRE) {
        Bh16 += (size_t)(z >> 4) * bZh + (size_t)(z & 15) * bZl;
        Bl16 += (size_t)(z >> 4) * bZh + (size_t)(z & 15) * bZl;
    } else {
        Bf += (size_t)(z >> 4) * bZh + (size_t)(z & 15) * bZl;
    }
    C += (size_t)(z >> 4) * cZh + (size_t)(z & 15) * cZl;

    int tid = threadIdx.x, lane = tid & 31, wid = tid >> 5;
    int wm = (wid & 1) * 64;
    int wn = (wid >> 1) * (BN / 4);

    float acc[4][NT8][4];
    #pragma unroll
    for (int i = 0; i < 4; ++i)
        #pragma unroll
        for (int j = 0; j < NT8; ++j)
            #pragma unroll
            for (int q = 0; q < 4; ++q) acc[i][j][q] = 0.f;

    float4 avS[4];
    float4 bvS[NBS];
    unsigned long long bhS[NBS], blS[NBS];

    uint32_t sbase = smem_u32(smem);
    uint32_t aAddr = sbase + SM_AH + (uint32_t)(wm + (lane & 15)) * STR + (lane >> 4) * 16;
    uint32_t bAddr = sbase + SM_BH + (uint32_t)(wn + (lane & 15)) * STR + (lane >> 4) * 16;

    int NC = K / 32;

    // ---- load chunk 0 ----
    {
        int kc = 0;
        #pragma unroll
        for (int i = 0; i < 4; ++i) {
            int slot = i * 256 + tid, r = slot >> 3, c4 = slot & 7;
            const float* p = A + (size_t)(m0 + r) * lda + kc + c4 * 4;
            if (AVEC) avS[i] = *(const float4*)p;
            else { avS[i].x = p[0]; avS[i].y = p[1]; avS[i].z = p[2]; avS[i].w = p[3]; }
        }
        if (BPRE) {
            #pragma unroll
            for (int i = 0; i < NBS; ++i) {
                int slot = i * 256 + tid, r = slot >> 3, q = slot & 7;
                const char* pb = (const char*)(Bh16 + (size_t)(n0 + r) * ldb + kc);
                const char* pl = (const char*)(Bl16 + (size_t)(n0 + r) * ldb + kc);
                bhS[i] = *(const unsigned long long*)(pb + q * 8);
                blS[i] = *(const unsigned long long*)(pl + q * 8);
            }
        } else {
            #pragma unroll
            for (int i = 0; i < NBS; ++i) {
                int slot = i * 256 + tid, r = slot >> 3, c4 = slot & 7;
                bvS[i] = *(const float4*)(Bf + (size_t)(n0 + r) * ldb + kc + c4 * 4);
            }
        }
    }

    for (int c = 0; c < NC; ++c) {
        if (c > 0) __syncthreads();
        // ---- store staged chunk to smem (with split) ----
        #pragma unroll
        for (int i = 0; i < 4; ++i) {
            int slot = i * 256 + tid, r = slot >> 3, c4 = slot & 7;
            uint32_t h01, l01, h23, l23;
            split2(avS[i].x, avS[i].y, h01, l01);
            split2(avS[i].z, avS[i].w, h23, l23);
            unsigned long long hv = (unsigned long long)h01 | ((unsigned long long)h23 << 32);
            unsigned long long lv = (unsigned long long)l01 | ((unsigned long long)l23 << 32);
            *(unsigned long long*)(smem + SM_AH + r * STR + c4 * 8) = hv;
            *(unsigned long long*)(smem + SM_AL + r * STR + c4 * 8) = lv;
        }
        if (BPRE) {
            #pragma unroll
            for (int i = 0; i < NBS; ++i) {
                int slot = i * 256 + tid, r = slot >> 3, q = slot & 7;
                *(unsigned long long*)(smem + SM_BH + r * STR + q * 8) = bhS[i];
                *(unsigned long long*)(smem + SM_BH + BN * STR + r * STR + q * 8) = blS[i];
            }
        } else {
            #pragma unroll
            for (int i = 0; i < NBS; ++i) {
                int slot = i * 256 + tid, r = slot >> 3, c4 = slot & 7;
                uint32_t h01, l01, h23, l23;
                split2(bvS[i].x, bvS[i].y, h01, l01);
                split2(bvS[i].z, bvS[i].w, h23, l23);
                unsigned long long hv = (unsigned long long)h01 | ((unsigned long long)h23 << 32);
                unsigned long long lv = (unsigned long long)l01 | ((unsigned long long)l23 << 32);
                *(unsigned long long*)(smem + SM_BH + r * STR + c4 * 8) = hv;
                *(unsigned long long*)(smem + SM_BH + BN * STR + r * STR + c4 * 8) = lv;
            }
        }
        __syncthreads();

        // ---- prefetch next chunk into registers ----
        if (c + 1 < NC) {
            int kc = (c + 1) * 32;
            #pragma unroll
            for (int i = 0; i < 4; ++i) {
                int slot = i * 256 + tid, r = slot >> 3, c4 = slot & 7;
                const float* p = A + (size_t)(m0 + r) * lda + kc + c4 * 4;
                if (AVEC) avS[i] = *(const float4*)p;
                else { avS[i].x = p[0]; avS[i].y = p[1]; avS[i].z = p[2]; avS[i].w = p[3]; }
            }
            if (BPRE) {
                #pragma unroll
                for (int i = 0; i < NBS; ++i) {
                    int slot = i * 256 + tid, r = slot >> 3, q = slot & 7;
                    const char* pb = (const char*)(Bh16 + (size_t)(n0 + r) * ldb + kc);
                    const char* pl = (const char*)(Bl16 + (size_t)(n0 + r) * ldb + kc);
                    bhS[i] = *(const unsigned long long*)(pb + q * 8);
                    blS[i] = *(const unsigned long long*)(pl + q * 8);
                }
            } else {
                #pragma unroll
                for (int i = 0; i < NBS; ++i) {
                    int slot = i * 256 + tid, r = slot >> 3, c4 = slot & 7;
                    bvS[i] = *(const float4*)(Bf + (size_t)(n0 + r) * ldb + kc + c4 * 4);
                }
            }
        }

        // ---- compute chunk c ----
        #pragma unroll
        for (int ks = 0; ks < 2; ++ks) {
            uint32_t ah[4][4], al[4][4];
            #pragma unroll
            for (int mt = 0; mt < 4; ++mt) {
                uint32_t base = aAddr + mt * 16 * STR + ks * 32;
                ldsm4(ah[mt][0], ah[mt][1], ah[mt][2], ah[mt][3], base);
                ldsm4(al[mt][0], al[mt][1], al[mt][2], al[mt][3], base + 128 * STR);
            }
            uint32_t bh[NT8][2], bl[NT8][2];
            #pragma unroll
            for (int g = 0; g < NB16; ++g) {
                uint32_t base = bAddr + g * 16 * STR + ks * 32;
                uint32_t r0, r1, r2, r3;
                ldsm4(r0, r1, r2, r3, base);
                bh[2*g][0] = r0; bh[2*g][1] = r2;
                bh[2*g+1][0] = r1; bh[2*g+1][1] = r3;
                ldsm4(r0, r1, r2, r3, base + BN * STR);
                bl[2*g][0] = r0; bl[2*g][1] = r2;
                bl[2*g+1][0] = r1; bl[2*g+1][1] = r3;
            }
            #pragma unroll
            for (int mt = 0; mt < 4; ++mt)
                #pragma unroll
                for (int n8 = 0; n8 < NT8; ++n8) {
                    mma16816(acc[mt][n8], ah[mt], bh[n8]);
                    mma16816(acc[mt][n8], ah[mt], bl[n8]);
                    mma16816(acc[mt][n8], al[mt], bh[n8]);
                }
        }
    }

    // ---- epilogue ----
    int gid = lane >> 2, tig = lane & 3;
    #pragma unroll
    for (int mt = 0; mt < 4; ++mt) {
        #pragma unroll
        for (int n8 = 0; n8 < NT8; ++n8) {
            int colb = n0 + wn + n8 * 8 + tig * 2;
            #pragma unroll
            for (int h2 = 0; h2 < 2; ++h2) {
                int m = m0 + wm + mt * 16 + gid + h2 * 8;
                #pragma unroll
                for (int cc = 0; cc < 2; ++cc) {
                    int n = colb + cc;
                    float v = acc[mt][n8][h2 * 2 + cc];
                    if (OMODE == 0) {
                        if (bias) v += bias[n];
                        if (resid) v += resid[(size_t)m * ldc + n];
                        if (relu) v = fmaxf(v, 0.f);
                        C[(size_t)m * ldc + n] = v;
                    } else if (OMODE == 1) {
                        C[(size_t)m * ldc + n] = v * 0.125f;
                    } else {
                        int b = m >> 10, t = m & 1023;
                        C[((size_t)((b * 16 + (n >> 6)) * 64 + (n & 63)) << 10) + t] = v;
                    }
                }
            }
        }
    }
}

// ---------------- SIMT helpers (embed/ln/softmax/loss) ----------------------
__global__ void embed_kernel(const int* __restrict__ idx,
                             const float* __restrict__ tok,
                             const float* __restrict__ pos) {
    size_t i = (size_t)blockIdx.x * 256 + threadIdx.x;
    int d  = (int)(i & (Dd - 1));
    int bt = (int)(i >> 10);
    int t  = bt & (Tt - 1);
    g_x[i] = tok[(size_t)idx[bt] * Dd + d] + pos[(size_t)t * Dd + d];
}

__global__ void ln_kernel(const float* __restrict__ x,
                          const float* __restrict__ g,
                          const float* __restrict__ b,
                          float* __restrict__ out) {
    __shared__ float s1[256], s2[256];
    int row = blockIdx.x;
    const float* xr = x + (size_t)row * Dd;
    int tid = threadIdx.x;
    float a = 0.f, a2 = 0.f;
    for (int i = tid; i < Dd; i += 256) { float v = xr[i]; a += v; a2 += v * v; }
    s1[tid] = a; s2[tid] = a2; __syncthreads();
    for (int s = 128; s > 0; s >>= 1) {
        if (tid < s) { s1[tid] += s1[tid + s]; s2[tid] += s2[tid + s]; }
        __syncthreads();
    }
    float mean = s1[0] * (1.f / Dd);
    float var  = s2[0] * (1.f / Dd) - mean * mean;
    float rstd = rsqrtf(var + EPSf);
    float* orow = out + (size_t)row * Dd;
    for (int i = tid; i < Dd; i += 256)
        orow[i] = (xr[i] - mean) * rstd * g[i] + b[i];
}

__global__ void softmax_kernel(float* __restrict__ attnL) {
    __shared__ float sd[256];
    int rgl = blockIdx.x;
    int bh = rgl >> 10, t = rgl & (Tt - 1);
    float* p = attnL + (size_t)bh * Tt * Tt + (size_t)t * Tt;
    int n = t + 1;
    int tid = threadIdx.x;
    float mx = -3.4e38f;
    for (int i = tid; i < n; i += 256) mx = fmaxf(mx, p[i]);
    sd[tid] = mx; __syncthreads();
    for (int s = 128; s > 0; s >>= 1) {
        if (tid < s) sd[tid] = fmaxf(sd[tid], sd[tid + s]);
        __syncthreads();
    }
    mx = sd[0]; __syncthreads();
    float sum = 0.f;
    for (int i = tid; i < n; i += 256) sum += __expf(p[i] - mx);
    sd[tid] = sum; __syncthreads();
    for (int s = 128; s > 0; s >>= 1) {
        if (tid < s) sd[tid] += sd[tid + s];
        __syncthreads();
    }
    float inv = 1.f / sd[0];
    for (int i = tid; i < Tt; i += 256)
        p[i] = (i < n) ? __expf(p[i] - mx) * inv : 0.f;
}

__global__ void loss_row_kernel(const int* __restrict__ targets) {
    __shared__ float sd[256];
    int r = blockIdx.x;
    const float* p = g_logits + (size_t)r * Vv;
    int tid = threadIdx.x;
    float mx = -3.4e38f;
    for (int i = tid; i < Vv; i += 256) mx = fmaxf(mx, p[i]);
    sd[tid] = mx; __syncthreads();
    for (int s = 128; s > 0; s >>= 1) {
        if (tid < s) sd[tid] = fmaxf(sd[tid], sd[tid + s]);
        __syncthreads();
    }
    mx = sd[0]; __syncthreads();
    float sum = 0.f;
    for (int i = tid; i < Vv; i += 256) sum += __expf(p[i] - mx);
    sd[tid] = sum; __syncthreads();
    for (int s = 128; s > 0; s >>= 1) {
        if (tid < s) sd[tid] += sd[tid + s];
        __syncthreads();
    }
    if (tid == 0)
        g_rownll[r] = logf(sd[0]) + mx - p[targets[r]];
}

__global__ void loss_final_kernel(float* __restrict__ out) {
    __shared__ float sd[256];
    int tid = threadIdx.x;
    float s = 0.f;
    for (int i = tid; i < BT; i += 256) s += g_rownll[i];
    sd[tid] = s; __syncthreads();
    for (int st = 128; st > 0; st >>= 1) {
        if (tid < st) sd[tid] += sd[tid + st];
        __syncthreads();
    }
    if (tid == 0) out[0] = sd[0] * (1.f / BT);
}

// ---------------- host orchestration ----------------------------------------
extern "C" void kernel_launch(void* const* d_in, const int* in_sizes, int n_in,
                              void* d_out, int out_size) {
    (void)in_sizes; (void)n_in; (void)out_size;
    const int*   idx     = (const int*)d_in[0];
    const int*   targets = (const int*)d_in[1];
    const float* tok     = (const float*)d_in[2];
    const float* pos     = (const float*)d_in[3];
    const float* ln1_g   = (const float*)d_in[4];
    const float* ln1_b   = (const float*)d_in[5];
    const float* Wq      = (const float*)d_in[6];
    const float* Wk      = (const float*)d_in[7];
    const float* Wv      = (const float*)d_in[8];
    const float* Wp      = (const float*)d_in[9];
    const float* bp      = (const float*)d_in[10];
    const float* ln2_g   = (const float*)d_in[11];
    const float* ln2_b   = (const float*)d_in[12];
    const float* W1      = (const float*)d_in[13];
    const float* b1      = (const float*)d_in[14];
    const float* W2      = (const float*)d_in[15];
    const float* b2      = (const float*)d_in[16];
    const float* lnf_g   = (const float*)d_in[17];
    const float* lnf_b   = (const float*)d_in[18];
    const float* Wlm     = (const float*)d_in[19];
    const float* blm     = (const float*)d_in[20];

    float* out  = (float*)d_out;
    float* attn = out + 1;   // [L,B,H,T,T], 4-byte aligned only

    float *px, *ph, *po, *pff, *plog, *pq, *pk, *pvT;
    cudaGetSymbolAddress((void**)&px,   g_x);
    cudaGetSymbolAddress((void**)&ph,   g_h);
    cudaGetSymbolAddress((void**)&po,   g_o);
    cudaGetSymbolAddress((void**)&pff,  g_ff);
    cudaGetSymbolAddress((void**)&plog, g_logits);
    cudaGetSymbolAddress((void**)&pq,   g_q);
    cudaGetSymbolAddress((void**)&pk,   g_k);
    cudaGetSymbolAddress((void**)&pvT,  g_vT);
    __nv_bfloat16 *wqh, *wql, *wkh, *wkl, *wvh, *wvl, *wph, *wpl,
                  *w1h, *w1l, *w2h, *w2l, *wlh, *wll;
    cudaGetSymbolAddress((void**)&wqh, g_wqT_h); cudaGetSymbolAddress((void**)&wql, g_wqT_l);
    cudaGetSymbolAddress((void**)&wkh, g_wkT_h); cudaGetSymbolAddress((void**)&wkl, g_wkT_l);
    cudaGetSymbolAddress((void**)&wvh, g_wvT_h); cudaGetSymbolAddress((void**)&wvl, g_wvT_l);
    cudaGetSymbolAddress((void**)&wph, g_wpT_h); cudaGetSymbolAddress((void**)&wpl, g_wpT_l);
    cudaGetSymbolAddress((void**)&w1h, g_w1T_h); cudaGetSymbolAddress((void**)&w1l, g_w1T_l);
    cudaGetSymbolAddress((void**)&w2h, g_w2T_h); cudaGetSymbolAddress((void**)&w2l, g_w2T_l);
    cudaGetSymbolAddress((void**)&wlh, g_wlmT_h); cudaGetSymbolAddress((void**)&wll, g_wlmT_l);

    dim3 wb(32, 8);
    wsplit_kernel<<<dim3(HSs/32, Dd/32, Ll*Hh), wb>>>(Wq, wqh, wql, Dd, HSs);
    wsplit_kernel<<<dim3(HSs/32, Dd/32, Ll*Hh), wb>>>(Wk, wkh, wkl, Dd, HSs);
    wsplit_kernel<<<dim3(HSs/32, Dd/32, Ll*Hh), wb>>>(Wv, wvh, wvl, Dd, HSs);
    wsplit_kernel<<<dim3(Dd/32,  Dd/32, Ll),    wb>>>(Wp, wph, wpl, Dd, Dd);
    wsplit_kernel<<<dim3(FFf/32, Dd/32, Ll),    wb>>>(W1, w1h, w1l, Dd, FFf);
    wsplit_kernel<<<dim3(Dd/32,  FFf/32, Ll),   wb>>>(W2, w2h, w2l, FFf, Dd);
    wsplit_kernel<<<dim3(Vv/32,  Dd/32, 1),     wb>>>(Wlm, wlh, wll, Dd, Vv);

    embed_kernel<<<BT * Dd / 256, 256>>>(idx, tok, pos);

    const size_t WQL = (size_t)Hh * HSs * Dd;   // per-layer qkv weight block
    for (int l = 0; l < Ll; ++l) {
        float* attnL = attn + (size_t)l * Bb * Hh * Tt * Tt;

        ln_kernel<<<BT, 256>>>(px, ln1_g + (size_t)l * Dd, ln1_b + (size_t)l * Dd, ph);

        // q, k: [4096 x 1024] = h @ W^T
        gmma_kernel<128, true, true, 0><<<dim3(32, 8, 1), 256>>>(
            ph, wqh + l * WQL, wql + l * WQL, pq, nullptr, nullptr, 0,
            Dd, Dd, Dd, Dd, 0, 0, 0, 0, 0, 0);
        gmma_kernel<128, true, true, 0><<<dim3(32, 8, 1), 256>>>(
            ph, wkh + l * WQL, wkl + l * WQL, pk, nullptr, nullptr, 0,
            Dd, Dd, Dd, Dd, 0, 0, 0, 0, 0, 0);
        // v: scatter-transposed into g_vT [bh][s][t]
        gmma_kernel<128, true, true, 2><<<dim3(32, 8, 1), 256>>>(
            ph, wvh + l * WQL, wvl + l * WQL, pvT, nullptr, nullptr, 0,
            Dd, Dd, Dd, Dd, 0, 0, 0, 0, 0, 0);

        // scores: per bh [1024x1024], K=64, causal tile skip, *0.125
        gmma_kernel<128, true, false, 1><<<dim3(8, 8, Bb * Hh), 256>>>(
            pq, pk, nullptr, attnL, nullptr, nullptr, 0,
            HSs, Dd, Dd, Tt,
            (size_t)Tt * Dd, HSs, (size_t)Tt * Dd, HSs,
            (size_t)16 * Tt * Tt, (size_t)Tt * Tt);

        softmax_kernel<<<Bb * Hh * Tt, 256>>>(attnL);

        // o = wei @ vT^T : per bh [1024x64], K=1024 (A misaligned -> scalar loads)
        gmma_kernel<64, false, false, 0><<<dim3(8, 1, Bb * Hh), 256>>>(
            attnL, pvT, nullptr, po, nullptr, nullptr, 0,
            Tt, Tt, Tt, Dd,
            (size_t)16 * Tt * Tt, (size_t)Tt * Tt,
            (size_t)16 * HSs * Tt, (size_t)HSs * Tt,
            (size_t)Tt * Dd, HSs);

        // x += o @ Wp + bp
        gmma_kernel<128, true, true, 0><<<dim3(32, 8, 1), 256>>>(
            po, wph + (size_t)l * Dd * Dd, wpl + (size_t)l * Dd * Dd, px,
            bp + (size_t)l * Dd, px, 0,
            Dd, Dd, Dd, Dd, 0, 0, 0, 0, 0, 0);

        ln_kernel<<<BT, 256>>>(px, ln2_g + (size_t)l * Dd, ln2_b + (size_t)l * Dd, ph);

        // ff = relu(h @ W1 + b1)
        gmma_kernel<128, true, true, 0><<<dim3(32, 32, 1), 256>>>(
            ph, w1h + (size_t)l * Dd * FFf, w1l + (size_t)l * Dd * FFf, pff,
            b1 + (size_t)l * FFf, nullptr, 1,
            Dd, Dd, Dd, FFf, 0, 0, 0, 0, 0, 0);

        // x += ff @ W2 + b2
        gmma_kernel<128, true, true, 0><<<dim3(32, 8, 1), 256>>>(
            pff, w2h + (size_t)l * FFf * Dd, w2l + (size_t)l * FFf * Dd, px,
            b2 + (size_t)l * Dd, px, 0,
            FFf, FFf, FFf, Dd, 0, 0, 0, 0, 0, 0);
    }

    ln_kernel<<<BT, 256>>>(px, lnf_g, lnf_b, ph);

    // logits = h @ Wlm + blm
    gmma_kernel<128, true, true, 0><<<dim3(32, 250, 1), 256>>>(
        ph, wlh, wll, plog, blm, nullptr, 0,
        Dd, Dd, Dd, Vv, 0, 0, 0, 0, 0, 0);

    loss_row_kernel<<<BT, 256>>>(targets);
    loss_final_kernel<<<1, 256>>>(out);
}

// round 7
// speedup vs baseline: 2.2524x; 1.1024x over previous
#include <cuda_runtime.h>
#include <cuda_bf16.h>
#include <math.h>
#include <stdint.h>

#define Bb   4
#define Tt   1024
#define Dd   1024
#define Hh   16
#define HSs  64
#define Ll   4
#define FFf  4096
#define Vv   32000
#define BT   (Bb*Tt)
#define EPSf 1e-5f

typedef __nv_bfloat16 bf16;

__device__ float g_x[BT*Dd];
__device__ float g_logits[(size_t)BT*Vv];
__device__ float g_rownll[BT];
__device__ __align__(16) bf16 g_hH[BT*Dd],  g_hL[BT*Dd];
__device__ __align__(16) bf16 g_qH[BT*Dd],  g_qL[BT*Dd];
__device__ __align__(16) bf16 g_kH[BT*Dd],  g_kL[BT*Dd];
__device__ __align__(16) bf16 g_vH[BT*Dd],  g_vL[BT*Dd];
__device__ __align__(16) bf16 g_oH[BT*Dd],  g_oL[BT*Dd];
__device__ __align__(16) bf16 g_ffH[(size_t)BT*FFf], g_ffL[(size_t)BT*FFf];
__device__ __align__(16) bf16 g_wH[(size_t)Bb*Hh*Tt*Tt], g_wL[(size_t)Bb*Hh*Tt*Tt];
__device__ __align__(16) bf16 g_wqT_h[Ll*Hh*HSs*Dd], g_wqT_l[Ll*Hh*HSs*Dd];
__device__ __align__(16) bf16 g_wkT_h[Ll*Hh*HSs*Dd], g_wkT_l[Ll*Hh*HSs*Dd];
__device__ __align__(16) bf16 g_wvT_h[Ll*Hh*HSs*Dd], g_wvT_l[Ll*Hh*HSs*Dd];
__device__ __align__(16) bf16 g_wpT_h[(size_t)Ll*Dd*Dd], g_wpT_l[(size_t)Ll*Dd*Dd];
__device__ __align__(16) bf16 g_w1T_h[(size_t)Ll*FFf*Dd], g_w1T_l[(size_t)Ll*FFf*Dd];
__device__ __align__(16) bf16 g_w2T_h[(size_t)Ll*Dd*FFf], g_w2T_l[(size_t)Ll*Dd*FFf];
__device__ __align__(16) bf16 g_wlmT_h[(size_t)Vv*Dd],    g_wlmT_l[(size_t)Vv*Dd];

__device__ __forceinline__ uint32_t smem_u32(const void* p) {
    uint32_t a;
    asm("{ .reg .u64 t; cvta.to.shared.u64 t, %1; cvt.u32.u64 %0, t; }" : "=r"(a) : "l"(p));
    return a;
}
__device__ __forceinline__ void ldsm4(uint32_t& r0, uint32_t& r1, uint32_t& r2,
                                      uint32_t& r3, uint32_t addr) {
    asm volatile("ldmatrix.sync.aligned.m8n8.x4.shared.b16 {%0,%1,%2,%3}, [%4];"
                 : "=r"(r0), "=r"(r1), "=r"(r2), "=r"(r3) : "r"(addr));
}
__device__ __forceinline__ void mma16816(float* c, const uint32_t* a, const uint32_t* b) {
    asm volatile(
        "mma.sync.aligned.m16n8k16.row.col.f32.bf16.bf16.f32 "
        "{%0,%1,%2,%3}, {%4,%5,%6,%7}, {%8,%9}, {%0,%1,%2,%3};"
        : "+f"(c[0]), "+f"(c[1]), "+f"(c[2]), "+f"(c[3])
        : "r"(a[0]), "r"(a[1]), "r"(a[2]), "r"(a[3]), "r"(b[0]), "r"(b[1]));
}
__device__ __forceinline__ void cpa16(uint32_t s, const void* g) {
    asm volatile("cp.async.cg.shared.global [%0], [%1], 16;" :: "r"(s), "l"(g));
}
__device__ __forceinline__ void cpa_commit() {
    asm volatile("cp.async.commit_group;" ::: "memory");
}
__device__ __forceinline__ void cpa_wait0() {
    asm volatile("cp.async.wait_group 0;" ::: "memory");
}
__device__ __forceinline__ void fsplit(float v, bf16& h, bf16& l) {
    h = __float2bfloat16(v);
    l = __float2bfloat16(v - __bfloat162float(h));
}

__global__ void wsplit_kernel(const float* __restrict__ W,
                              bf16* __restrict__ Whi, bf16* __restrict__ Wlo,
                              int R, int C) {
    __shared__ float ts[32][33];
    size_t mo = (size_t)blockIdx.z * R * C;
    int c0 = blockIdx.x * 32, r0 = blockIdx.y * 32;
    int tx = threadIdx.x, ty = threadIdx.y;
    #pragma unroll
    for (int i = 0; i < 4; ++i) {
        int r = r0 + ty + i * 8;
        ts[ty + i * 8][tx] = W[mo + (size_t)r * C + c0 + tx];
    }
    __syncthreads();
    #pragma unroll
    for (int i = 0; i < 4; ++i) {
        int n = c0 + ty + i * 8;
        int k = r0 + tx;
        bf16 h, l; fsplit(ts[tx][ty + i * 8], h, l);
        Whi[mo + (size_t)n * R + k] = h;
        Wlo[mo + (size_t)n * R + k] = l;
    }
}

// OMODE 0: fp32 +bias/resid/relu | 1: scores | 2: vT scatter | 3: bf16 linear | 4: qk scatter
template<int BN, int OMODE>
__global__ __launch_bounds__(256, 2)
void gmma_kernel(const bf16* __restrict__ Ah, const bf16* __restrict__ Al,
                 const bf16* __restrict__ Bh, const bf16* __restrict__ Bl,
                 float* __restrict__ C, bf16* __restrict__ Ch, bf16* __restrict__ Cl,
                 const float* __restrict__ bias, const float* __restrict__ resid,
                 int relu, int K, int lda, int ldb, int ldc,
                 size_t aZh, size_t aZl, size_t bZh, size_t bZl,
                 size_t cZh, size_t cZl) {
    constexpr int STR = 80;
    constexpr int ALO = 128 * STR;
    constexpr int BHO = 256 * STR;
    constexpr int BLO = BHO + BN * STR;
    constexpr int SSZ = BHO + 2 * BN * STR;
    constexpr int NT8 = BN / 32;
    constexpr int NB16 = NT8 / 2;
    constexpr int BSEG = BN * 4 / 256;
    extern __shared__ __align__(16) unsigned char smem[];

    int m0 = blockIdx.x * 128, n0 = blockIdx.y * BN;
    if (OMODE == 1 && n0 > m0) return;
    int z = blockIdx.z;
    Ah += (size_t)(z >> 4) * aZh + (size_t)(z & 15) * aZl;
    Al += (size_t)(z >> 4) * aZh + (size_t)(z & 15) * aZl;
    Bh += (size_t)(z >> 4) * bZh + (size_t)(z & 15) * bZl;
    Bl += (size_t)(z >> 4) * bZh + (size_t)(z & 15) * bZl;
    if (OMODE == 0 || OMODE == 1)
        C += (size_t)(z >> 4) * cZh + (size_t)(z & 15) * cZl;
    else {
        Ch += (size_t)(z >> 4) * cZh + (size_t)(z & 15) * cZl;
        Cl += (size_t)(z >> 4) * cZh + (size_t)(z & 15) * cZl;
    }

    int tid = threadIdx.x, lane = tid & 31, wid = tid >> 5;
    int wm = (wid & 1) * 64;
    int wn = (wid >> 1) * (BN / 4);

    float acc[4][NT8][4];
    #pragma unroll
    for (int i = 0; i < 4; ++i)
        #pragma unroll
        for (int j = 0; j < NT8; ++j)
            #pragma unroll
            for (int q = 0; q < 4; ++q) acc[i][j][q] = 0.f;

    uint32_t sbase = smem_u32(smem);
    int NC = K / 32;

    auto load_stage = [&](int c) {
        uint32_t stg = sbase + (uint32_t)(c & 1) * SSZ;
        int kc = c * 32;
        #pragma unroll
        for (int i = 0; i < 2; ++i) {
            int slot = i * 256 + tid, r = slot >> 2, sg = slot & 3;
            uint32_t so = r * STR + sg * 16;
            size_t go = (size_t)(m0 + r) * lda + kc + sg * 8;
            cpa16(stg + so, Ah + go);
            cpa16(stg + ALO + so, Al + go);
        }
        #pragma unroll
        for (int i = 0; i < BSEG; ++i) {
            int slot = i * 256 + tid, r = slot >> 2, sg = slot & 3;
            uint32_t so = r * STR + sg * 16;
            size_t go = (size_t)(n0 + r) * ldb + kc + sg * 8;
            cpa16(stg + BHO + so, Bh + go);
            cpa16(stg + BLO + so, Bl + go);
        }
        cpa_commit();
    };

    load_stage(0);
    uint32_t aAddr0 = sbase + (uint32_t)(wm + (lane & 15)) * STR + (lane >> 4) * 16;
    uint32_t bAddr0 = sbase + BHO + (uint32_t)(wn + (lane & 15)) * STR + (lane >> 4) * 16;

    for (int c = 0; c < NC; ++c) {
        cpa_wait0();
        __syncthreads();
        if (c + 1 < NC) load_stage(c + 1);
        uint32_t stg = (uint32_t)(c & 1) * SSZ;
        uint32_t aAddr = aAddr0 + stg, bAddr = bAddr0 + stg;
        #pragma unroll
        for (int ks = 0; ks < 2; ++ks) {
            uint32_t ah[4][4], al[4][4];
            #pragma unroll
            for (int mt = 0; mt < 4; ++mt) {
                uint32_t base = aAddr + mt * 16 * STR + ks * 32;
                ldsm4(ah[mt][0], ah[mt][1], ah[mt][2], ah[mt][3], base);
                ldsm4(al[mt][0], al[mt][1], al[mt][2], al[mt][3], base + ALO);
            }
            uint32_t bh[NT8][2], bl[NT8][2];
            #pragma unroll
            for (int g = 0; g < NB16; ++g) {
                uint32_t base = bAddr + g * 16 * STR + ks * 32;
                uint32_t r0, r1, r2, r3;
                ldsm4(r0, r1, r2, r3, base);
                bh[2*g][0] = r0; bh[2*g][1] = r2;
                bh[2*g+1][0] = r1; bh[2*g+1][1] = r3;
                ldsm4(r0, r1, r2, r3, base + BN * STR);
                bl[2*g][0] = r0; bl[2*g][1] = r2;
                bl[2*g+1][0] = r1; bl[2*g+1][1] = r3;
            }
            #pragma unroll
            for (int mt = 0; mt < 4; ++mt)
                #pragma unroll
                for (int n8 = 0; n8 < NT8; ++n8) {
                    mma16816(acc[mt][n8], ah[mt], bh[n8]);
                    mma16816(acc[mt][n8], ah[mt], bl[n8]);
                    mma16816(acc[mt][n8], al[mt], bh[n8]);
                }
        }
        __syncthreads();
    }

    int gid = lane >> 2, tig = lane & 3;
    #pragma unroll
    for (int mt = 0; mt < 4; ++mt) {
        #pragma unroll
        for (int n8 = 0; n8 < NT8; ++n8) {
            int colb = n0 + wn + n8 * 8 + tig * 2;
            #pragma unroll
            for (int h2 = 0; h2 < 2; ++h2) {
                int m = m0 + wm + mt * 16 + gid + h2 * 8;
                #pragma unroll
                for (int cc = 0; cc < 2; ++cc) {
                    int n = colb + cc;
                    float v = acc[mt][n8][h2 * 2 + cc];
                    if (OMODE == 0) {
                        if (bias) v += bias[n];
                        if (resid) v += resid[(size_t)m * ldc + n];
                        if (relu) v = fmaxf(v, 0.f);
                        C[(size_t)m * ldc + n] = v;
                    } else if (OMODE == 1) {
                        C[(size_t)m * ldc + n] = v * 0.125f;
                    } else if (OMODE == 3) {
                        if (bias) v += bias[n];
                        if (relu) v = fmaxf(v, 0.f);
                        bf16 h, l; fsplit(v, h, l);
                        Ch[(size_t)m * ldc + n] = h;
                        Cl[(size_t)m * ldc + n] = l;
                    } else if (OMODE == 2) {
                        int b = m >> 10, t = m & 1023;
                        size_t o = ((size_t)((b * 16 + (n >> 6)) * 64 + (n & 63)) << 10) + t;
                        bf16 h, l; fsplit(v, h, l);
                        Ch[o] = h; Cl[o] = l;
                    } else {
                        int b = m >> 10, t = m & 1023;
                        size_t o = (size_t)(((b * 16 + (n >> 6)) << 10) + t) * 64 + (n & 63);
                        bf16 h, l; fsplit(v, h, l);
                        Ch[o] = h; Cl[o] = l;
                    }
                }
            }
        }
    }
}

__global__ void embed_kernel(const int* __restrict__ idx,
                             const float* __restrict__ tok,
                             const float* __restrict__ pos) {
    size_t i = (size_t)blockIdx.x * 256 + threadIdx.x;
    int d  = (int)(i & (Dd - 1));
    int bt = (int)(i >> 10);
    int t  = bt & (Tt - 1);
    g_x[i] = tok[(size_t)idx[bt] * Dd + d] + pos[(size_t)t * Dd + d];
}

__global__ void ln_kernel(const float* __restrict__ x,
                          const float* __restrict__ g,
                          const float* __restrict__ b,
                          bf16* __restrict__ oh, bf16* __restrict__ ol) {
    __shared__ float s1[256], s2[256];
    int row = blockIdx.x;
    const float* xr = x + (size_t)row * Dd;
    int tid = threadIdx.x;
    float a = 0.f, a2 = 0.f;
    for (int i = tid; i < Dd; i += 256) { float v = xr[i]; a += v; a2 += v * v; }
    s1[tid] = a; s2[tid] = a2; __syncthreads();
    for (int s = 128; s > 0; s >>= 1) {
        if (tid < s) { s1[tid] += s1[tid + s]; s2[tid] += s2[tid + s]; }
        __syncthreads();
    }
    float mean = s1[0] * (1.f / Dd);
    float var  = s2[0] * (1.f / Dd) - mean * mean;
    float rstd = rsqrtf(var + EPSf);
    for (int i = tid; i < Dd; i += 256) {
        float v = (xr[i] - mean) * rstd * g[i] + b[i];
        bf16 h, l; fsplit(v, h, l);
        oh[(size_t)row * Dd + i] = h;
        ol[(size_t)row * Dd + i] = l;
    }
}

__global__ void softmax_kernel(float* __restrict__ attnL,
                               bf16* __restrict__ WH, bf16* __restrict__ WL) {
    __shared__ float sm[8];
    int rgl = blockIdx.x;
    int bh = rgl >> 10, t = rgl & (Tt - 1);
    size_t off = ((size_t)bh << 20) + ((size_t)t << 10);
    float* p = attnL + off;
    bf16* wh = WH + off;
    bf16* wl = WL + off;
    int tid = threadIdx.x, lane = tid & 31, wrp = tid >> 5;
    float v[4];
    float mx = -3.4e38f;
    #pragma unroll
    for (int k = 0; k < 4; ++k) {
        int i = k * 256 + tid;
        float x = p[i];
        v[k] = (i <= t) ? x : -3.4e38f;
        mx = fmaxf(mx, v[k]);
    }
    #pragma unroll
    for (int o = 16; o > 0; o >>= 1) mx = fmaxf(mx, __shfl_xor_sync(~0u, mx, o));
    if (lane == 0) sm[wrp] = mx;
    __syncthreads();
    mx = sm[0];
    #pragma unroll
    for (int w = 1; w < 8; ++w) mx = fmaxf(mx, sm[w]);
    float e[4], s = 0.f;
    #pragma unroll
    for (int k = 0; k < 4; ++k) {
        int i = k * 256 + tid;
        e[k] = (i <= t) ? __expf(v[k] - mx) : 0.f;
        s += e[k];
    }
    #pragma unroll
    for (int o = 16; o > 0; o >>= 1) s += __shfl_xor_sync(~0u, s, o);
    __syncthreads();
    if (lane == 0) sm[wrp] = s;
    __syncthreads();
    s = 0.f;
    #pragma unroll
    for (int w = 0; w < 8; ++w) s += sm[w];
    float inv = 1.f / s;
    #pragma unroll
    for (int k = 0; k < 4; ++k) {
        int i = k * 256 + tid;
        float r = e[k] * inv;
        p[i] = r;
        bf16 h, l; fsplit(r, h, l);
        wh[i] = h; wl[i] = l;
    }
}

__global__ void loss_row_kernel(const int* __restrict__ targets) {
    __shared__ float sd[256];
    int r = blockIdx.x;
    const float* p = g_logits + (size_t)r * Vv;
    int tid = threadIdx.x;
    float mx = -3.4e38f;
    for (int i = tid; i < Vv; i += 256) mx = fmaxf(mx, p[i]);
    sd[tid] = mx; __syncthreads();
    for (int s = 128; s > 0; s >>= 1) {
        if (tid < s) sd[tid] = fmaxf(sd[tid], sd[tid + s]);
        __syncthreads();
    }
    mx = sd[0]; __syncthreads();
    float sum = 0.f;
    for (int i = tid; i < Vv; i += 256) sum += __expf(p[i] - mx);
    sd[tid] = sum; __syncthreads();
    for (int s = 128; s > 0; s >>= 1) {
        if (tid < s) sd[tid] += sd[tid + s];
        __syncthreads();
    }
    if (tid == 0)
        g_rownll[r] = logf(sd[0]) + mx - p[targets[r]];
}

__global__ void loss_final_kernel(float* __restrict__ out) {
    __shared__ float sd[256];
    int tid = threadIdx.x;
    float s = 0.f;
    for (int i = tid; i < BT; i += 256) s += g_rownll[i];
    sd[tid] = s; __syncthreads();
    for (int st = 128; st > 0; st >>= 1) {
        if (tid < st) sd[tid] += sd[tid + st];
        __syncthreads();
    }
    if (tid == 0) out[0] = sd[0] * (1.f / BT);
}

#define SM128 (2 * ((256 + 2 * 128) * 80))
#define SM64  (2 * ((256 + 2 * 64) * 80))

extern "C" void kernel_launch(void* const* d_in, const int* in_sizes, int n_in,
                              void* d_out, int out_size) {
    (void)in_sizes; (void)n_in; (void)out_size;
    const int*   idx     = (const int*)d_in[0];
    const int*   targets = (const int*)d_in[1];
    const float* tok     = (const float*)d_in[2];
    const float* pos     = (const float*)d_in[3];
    const float* ln1_g   = (const float*)d_in[4];
    const float* ln1_b   = (const float*)d_in[5];
    const float* Wq      = (const float*)d_in[6];
    const float* Wk      = (const float*)d_in[7];
    const float* Wv      = (const float*)d_in[8];
    const float* Wp      = (const float*)d_in[9];
    const float* bp      = (const float*)d_in[10];
    const float* ln2_g   = (const float*)d_in[11];
    const float* ln2_b   = (const float*)d_in[12];
    const float* W1      = (const float*)d_in[13];
    const float* b1      = (const float*)d_in[14];
    const float* W2      = (const float*)d_in[15];
    const float* b2      = (const float*)d_in[16];
    const float* lnf_g   = (const float*)d_in[17];
    const float* lnf_b   = (const float*)d_in[18];
    const float* Wlm     = (const float*)d_in[19];
    const float* blm     = (const float*)d_in[20];

    float* out  = (float*)d_out;
    float* attn = out + 1;

    cudaFuncSetAttribute(gmma_kernel<128, 0>, cudaFuncAttributeMaxDynamicSharedMemorySize, SM128);
    cudaFuncSetAttribute(gmma_kernel<128, 1>, cudaFuncAttributeMaxDynamicSharedMemorySize, SM128);
    cudaFuncSetAttribute(gmma_kernel<128, 2>, cudaFuncAttributeMaxDynamicSharedMemorySize, SM128);
    cudaFuncSetAttribute(gmma_kernel<128, 3>, cudaFuncAttributeMaxDynamicSharedMemorySize, SM128);
    cudaFuncSetAttribute(gmma_kernel<128, 4>, cudaFuncAttributeMaxDynamicSharedMemorySize, SM128);
    cudaFuncSetAttribute(gmma_kernel<64,  3>, cudaFuncAttributeMaxDynamicSharedMemorySize, SM64);

    float *px, *plog;
    cudaGetSymbolAddress((void**)&px,   g_x);
    cudaGetSymbolAddress((void**)&plog, g_logits);
    bf16 *hH,*hL,*qH,*qL,*kH,*kL,*vH,*vL,*oH,*oL,*fH,*fL,*wH,*wL;
    cudaGetSymbolAddress((void**)&hH, g_hH); cudaGetSymbolAddress((void**)&hL, g_hL);
    cudaGetSymbolAddress((void**)&qH, g_qH); cudaGetSymbolAddress((void**)&qL, g_qL);
    cudaGetSymbolAddress((void**)&kH, g_kH); cudaGetSymbolAddress((void**)&kL, g_kL);
    cudaGetSymbolAddress((void**)&vH, g_vH); cudaGetSymbolAddress((void**)&vL, g_vL);
    cudaGetSymbolAddress((void**)&oH, g_oH); cudaGetSymbolAddress((void**)&oL, g_oL);
    cudaGetSymbolAddress((void**)&fH, g_ffH); cudaGetSymbolAddress((void**)&fL, g_ffL);
    cudaGetSymbolAddress((void**)&wH, g_wH); cudaGetSymbolAddress((void**)&wL, g_wL);
    bf16 *wqh,*wql,*wkh,*wkl,*wvh,*wvl,*wph,*wpl,*w1h,*w1l,*w2h,*w2l,*wlh,*wll;
    cudaGetSymbolAddress((void**)&wqh, g_wqT_h); cudaGetSymbolAddress((void**)&wql, g_wqT_l);
    cudaGetSymbolAddress((void**)&wkh, g_wkT_h); cudaGetSymbolAddress((void**)&wkl, g_wkT_l);
    cudaGetSymbolAddress((void**)&wvh, g_wvT_h); cudaGetSymbolAddress((void**)&wvl, g_wvT_l);
    cudaGetSymbolAddress((void**)&wph, g_wpT_h); cudaGetSymbolAddress((void**)&wpl, g_wpT_l);
    cudaGetSymbolAddress((void**)&w1h, g_w1T_h); cudaGetSymbolAddress((void**)&w1l, g_w1T_l);
    cudaGetSymbolAddress((void**)&w2h, g_w2T_h); cudaGetSymbolAddress((void**)&w2l, g_w2T_l);
    cudaGetSymbolAddress((void**)&wlh, g_wlmT_h); cudaGetSymbolAddress((void**)&wll, g_wlmT_l);

    dim3 wb(32, 8);
    wsplit_kernel<<<dim3(HSs/32, Dd/32, Ll*Hh), wb>>>(Wq, wqh, wql, Dd, HSs);
    wsplit_kernel<<<dim3(HSs/32, Dd/32, Ll*Hh), wb>>>(Wk, wkh, wkl, Dd, HSs);
    wsplit_kernel<<<dim3(HSs/32, Dd/32, Ll*Hh), wb>>>(Wv, wvh, wvl, Dd, HSs);
    wsplit_kernel<<<dim3(Dd/32,  Dd/32, Ll),    wb>>>(Wp, wph, wpl, Dd, Dd);
    wsplit_kernel<<<dim3(FFf/32, Dd/32, Ll),    wb>>>(W1, w1h, w1l, Dd, FFf);
    wsplit_kernel<<<dim3(Dd/32,  FFf/32, Ll),   wb>>>(W2, w2h, w2l, FFf, Dd);
    wsplit_kernel<<<dim3(Vv/32,  Dd/32, 1),     wb>>>(Wlm, wlh, wll, Dd, Vv);

    embed_kernel<<<BT * Dd / 256, 256>>>(idx, tok, pos);

    const size_t WQL = (size_t)Hh * HSs * Dd;
    for (int l = 0; l < Ll; ++l) {
        float* attnL = attn + (size_t)l * Bb * Hh * Tt * Tt;

        ln_kernel<<<BT, 256>>>(px, ln1_g + (size_t)l * Dd, ln1_b + (size_t)l * Dd, hH, hL);

        gmma_kernel<128, 4><<<dim3(32, 8, 1), 256, SM128>>>(
            hH, hL, wqh + l * WQL, wql + l * WQL, nullptr, qH, qL,
            nullptr, nullptr, 0, Dd, Dd, Dd, 0, 0, 0, 0, 0, 0, 0);
        gmma_kernel<128, 4><<<dim3(32, 8, 1), 256, SM128>>>(
            hH, hL, wkh + l * WQL, wkl + l * WQL, nullptr, kH, kL,
            nullptr, nullptr, 0, Dd, Dd, Dd, 0, 0, 0, 0, 0, 0, 0);
        gmma_kernel<128, 2><<<dim3(32, 8, 1), 256, SM128>>>(
            hH, hL, wvh + l * WQL, wvl + l * WQL, nullptr, vH, vL,
            nullptr, nullptr, 0, Dd, Dd, Dd, 0, 0, 0, 0, 0, 0, 0);

        // scores: A=q [bh][t][64], B=k [bh][t][64], C=attnL fp32
        gmma_kernel<128, 1><<<dim3(8, 8, Bb * Hh), 256, SM128>>>(
            qH, qL, kH, kL, attnL, nullptr, nullptr, nullptr, nullptr, 0,
            HSs, HSs, HSs, Tt,
            (size_t)16 * Tt * HSs, (size_t)Tt * HSs,
            (size_t)16 * Tt * HSs, (size_t)Tt * HSs,
            (size_t)16 * Tt * Tt, (size_t)Tt * Tt);

        softmax_kernel<<<Bb * Hh * Tt, 256>>>(attnL, wH, wL);

        gmma_kernel<64, 3><<<dim3(8, 1, Bb * Hh), 256, SM64>>>(
            wH, wL, vH, vL, nullptr, oH, oL, nullptr, nullptr, 0,
            Tt, Tt, Tt, Dd,
            (size_t)16 * Tt * Tt, (size_t)Tt * Tt,
            (size_t)16 * HSs * Tt, (size_t)HSs * Tt,
            (size_t)Tt * Dd, HSs);

        gmma_kernel<128, 0><<<dim3(32, 8, 1), 256, SM128>>>(
            oH, oL, wph + (size_t)l * Dd * Dd, wpl + (size_t)l * Dd * Dd,
            px, nullptr, nullptr, bp + (size_t)l * Dd, px, 0,
            Dd, Dd, Dd, Dd, 0, 0, 0, 0, 0, 0);

        ln_kernel<<<BT, 256>>>(px, ln2_g + (size_t)l * Dd, ln2_b + (size_t)l * Dd, hH, hL);

        gmma_kernel<128, 3><<<dim3(32, 32, 1), 256, SM128>>>(
            hH, hL, w1h + (size_t)l * Dd * FFf, w1l + (size_t)l * Dd * FFf,
            nullptr, fH, fL, b1 + (size_t)l * FFf, nullptr, 1,
            Dd, Dd, Dd, FFf, 0, 0, 0, 0, 0, 0);

        gmma_kernel<128, 0><<<dim3(32, 8, 1), 256, SM128>>>(
            fH, fL, w2h + (size_t)l * FFf * Dd, w2l + (size_t)l * FFf * Dd,
            px, nullptr, nullptr, b2 + (size_t)l * Dd, px, 0,
            FFf, FFf, FFf, Dd, 0, 0, 0, 0, 0, 0);
    }

    ln_kernel<<<BT, 256>>>(px, lnf_g, lnf_b, hH, hL);

    gmma_kernel<128, 0><<<dim3(32, 250, 1), 256, SM128>>>(
        hH, hL, wlh, wll, plog, nullptr, nullptr, blm, nullptr, 0,
        Dd, Dd, Dd, Vv, 0, 0, 0, 0, 0, 0);

    loss_row_kernel<<<BT, 256>>>(targets);
    loss_final_kernel<<<1, 256>>>(out);
}

// round 8
// speedup vs baseline: 2.2935x; 1.0183x over previous
#include <cuda_runtime.h>
#include <cuda_bf16.h>
#include <math.h>
#include <stdint.h>

#define Bb   4
#define Tt   1024
#define Dd   1024
#define Hh   16
#define HSs  64
#define Ll   4
#define FFf  4096
#define Vv   32000
#define BT   (Bb*Tt)
#define EPSf 1e-5f

typedef __nv_bfloat16 bf16;

__device__ float g_x[BT*Dd];
__device__ float g_logits[(size_t)BT*Vv];
__device__ float g_rownll[BT];
__device__ __align__(16) bf16 g_hH[BT*Dd],  g_hL[BT*Dd];
__device__ __align__(16) bf16 g_qH[BT*Dd],  g_qL[BT*Dd];
__device__ __align__(16) bf16 g_kH[BT*Dd],  g_kL[BT*Dd];
__device__ __align__(16) bf16 g_vH[BT*Dd],  g_vL[BT*Dd];
__device__ __align__(16) bf16 g_oH[BT*Dd],  g_oL[BT*Dd];
__device__ __align__(16) bf16 g_ffH[(size_t)BT*FFf], g_ffL[(size_t)BT*FFf];
__device__ __align__(16) bf16 g_wH[(size_t)Bb*Hh*Tt*Tt], g_wL[(size_t)Bb*Hh*Tt*Tt];
__device__ __align__(16) bf16 g_wqT_h[Ll*Hh*HSs*Dd], g_wqT_l[Ll*Hh*HSs*Dd];
__device__ __align__(16) bf16 g_wkT_h[Ll*Hh*HSs*Dd], g_wkT_l[Ll*Hh*HSs*Dd];
__device__ __align__(16) bf16 g_wvT_h[Ll*Hh*HSs*Dd], g_wvT_l[Ll*Hh*HSs*Dd];
__device__ __align__(16) bf16 g_wpT_h[(size_t)Ll*Dd*Dd], g_wpT_l[(size_t)Ll*Dd*Dd];
__device__ __align__(16) bf16 g_w1T_h[(size_t)Ll*FFf*Dd], g_w1T_l[(size_t)Ll*FFf*Dd];
__device__ __align__(16) bf16 g_w2T_h[(size_t)Ll*Dd*FFf], g_w2T_l[(size_t)Ll*Dd*FFf];
__device__ __align__(16) bf16 g_wlmT_h[(size_t)Vv*Dd],    g_wlmT_l[(size_t)Vv*Dd];

__device__ __forceinline__ uint32_t smem_u32(const void* p) {
    uint32_t a;
    asm("{ .reg .u64 t; cvta.to.shared.u64 t, %1; cvt.u32.u64 %0, t; }" : "=r"(a) : "l"(p));
    return a;
}
__device__ __forceinline__ void ldsm4(uint32_t& r0, uint32_t& r1, uint32_t& r2,
                                      uint32_t& r3, uint32_t addr) {
    asm volatile("ldmatrix.sync.aligned.m8n8.x4.shared.b16 {%0,%1,%2,%3}, [%4];"
                 : "=r"(r0), "=r"(r1), "=r"(r2), "=r"(r3) : "r"(addr));
}
__device__ __forceinline__ void mma16816(float* c, const uint32_t* a, const uint32_t* b) {
    asm volatile(
        "mma.sync.aligned.m16n8k16.row.col.f32.bf16.bf16.f32 "
        "{%0,%1,%2,%3}, {%4,%5,%6,%7}, {%8,%9}, {%0,%1,%2,%3};"
        : "+f"(c[0]), "+f"(c[1]), "+f"(c[2]), "+f"(c[3])
        : "r"(a[0]), "r"(a[1]), "r"(a[2]), "r"(a[3]), "r"(b[0]), "r"(b[1]));
}
__device__ __forceinline__ void cpa16(uint32_t s, const void* g) {
    asm volatile("cp.async.cg.shared.global [%0], [%1], 16;" :: "r"(s), "l"(g));
}
__device__ __forceinline__ void cpa_commit() {
    asm volatile("cp.async.commit_group;" ::: "memory");
}
__device__ __forceinline__ void cpa_wait0() {
    asm volatile("cp.async.wait_group 0;" ::: "memory");
}
__device__ __forceinline__ void fsplit(float v, bf16& h, bf16& l) {
    h = __float2bfloat16(v);
    l = __float2bfloat16(v - __bfloat162float(h));
}

// ---------------- fused weight transpose + split (up to 4 weights) ----------
struct WSDesc { const float* W; bf16* H; bf16* L; int R, C, nz; };

__global__ void wsplit_multi(WSDesc d0, WSDesc d1, WSDesc d2, WSDesc d3,
                             int nb0, int nb1, int nb2, int nb3) {
    __shared__ float ts[32][33];
    int id = blockIdx.x;
    WSDesc d;
    if (id < nb0) { d = d0; }
    else if (id < nb0 + nb1) { d = d1; id -= nb0; }
    else if (id < nb0 + nb1 + nb2) { d = d2; id -= nb0 + nb1; }
    else { d = d3; id -= nb0 + nb1 + nb2; }
    int nbx = d.C >> 5, nby = d.R >> 5;
    int z = id / (nbx * nby);
    int rem = id - z * nbx * nby;
    int by = rem / nbx, bx = rem - by * nbx;
    size_t mo = (size_t)z * d.R * d.C;
    int c0 = bx * 32, r0 = by * 32;
    int tx = threadIdx.x, ty = threadIdx.y;
    #pragma unroll
    for (int i = 0; i < 4; ++i) {
        int r = r0 + ty + i * 8;
        ts[ty + i * 8][tx] = d.W[mo + (size_t)r * d.C + c0 + tx];
    }
    __syncthreads();
    #pragma unroll
    for (int i = 0; i < 4; ++i) {
        int n = c0 + ty + i * 8;
        int k = r0 + tx;
        bf16 h, l; fsplit(ts[tx][ty + i * 8], h, l);
        d.H[mo + (size_t)n * d.R + k] = h;
        d.L[mo + (size_t)n * d.R + k] = l;
    }
}

// ---------------- unified bf16 hi/lo tensor-core GEMM -----------------------
// OMODE 0: fp32 +bias/resid/relu | 1: scores | 3: bf16 linear | 5: fused QKV
struct QKVP {
    const bf16 *bh0, *bl0, *bh1, *bl1, *bh2, *bl2;
    bf16 *ch0, *cl0, *ch1, *cl1, *ch2, *cl2;
};

template<int BN, int OMODE>
__global__ __launch_bounds__(256, 2)
void gmma_kernel(const bf16* __restrict__ Ah, const bf16* __restrict__ Al,
                 const bf16* __restrict__ Bhp, const bf16* __restrict__ Blp,
                 float* __restrict__ C, bf16* __restrict__ Chp, bf16* __restrict__ Clp,
                 const float* __restrict__ bias, const float* __restrict__ resid,
                 int relu, int K, int lda, int ldb, int ldc,
                 size_t aZh, size_t aZl, size_t bZh, size_t bZl,
                 size_t cZh, size_t cZl, QKVP qp) {
    constexpr int STR = 80;
    constexpr int ALO = 128 * STR;
    constexpr int BHO = 256 * STR;
    constexpr int BLO = BHO + BN * STR;
    constexpr int SSZ = BHO + 2 * BN * STR;
    constexpr int NT8 = BN / 32;
    constexpr int NB16 = NT8 / 2;
    constexpr int BSEG = BN * 4 / 256;
    extern __shared__ __align__(16) unsigned char smem[];

    int m0 = blockIdx.x * 128, n0 = blockIdx.y * BN;
    if (OMODE == 1 && n0 > m0) return;
    int z = blockIdx.z;
    const bf16 *Bh, *Bl;
    bf16 *Ch = nullptr, *Cl = nullptr;
    if (OMODE == 5) {
        if (z == 0)      { Bh = qp.bh0; Bl = qp.bl0; Ch = qp.ch0; Cl = qp.cl0; }
        else if (z == 1) { Bh = qp.bh1; Bl = qp.bl1; Ch = qp.ch1; Cl = qp.cl1; }
        else             { Bh = qp.bh2; Bl = qp.bl2; Ch = qp.ch2; Cl = qp.cl2; }
    } else {
        Ah += (size_t)(z >> 4) * aZh + (size_t)(z & 15) * aZl;
        Al += (size_t)(z >> 4) * aZh + (size_t)(z & 15) * aZl;
        Bh = Bhp + (size_t)(z >> 4) * bZh + (size_t)(z & 15) * bZl;
        Bl = Blp + (size_t)(z >> 4) * bZh + (size_t)(z & 15) * bZl;
        if (OMODE == 0 || OMODE == 1)
            C += (size_t)(z >> 4) * cZh + (size_t)(z & 15) * cZl;
        else {
            Ch = Chp + (size_t)(z >> 4) * cZh + (size_t)(z & 15) * cZl;
            Cl = Clp + (size_t)(z >> 4) * cZh + (size_t)(z & 15) * cZl;
        }
    }

    int tid = threadIdx.x, lane = tid & 31, wid = tid >> 5;
    int wm = (wid & 1) * 64;
    int wn = (wid >> 1) * (BN / 4);

    float acc[4][NT8][4];
    #pragma unroll
    for (int i = 0; i < 4; ++i)
        #pragma unroll
        for (int j = 0; j < NT8; ++j)
            #pragma unroll
            for (int q = 0; q < 4; ++q) acc[i][j][q] = 0.f;

    uint32_t sbase = smem_u32(smem);
    int NC = K / 32;

    auto load_stage = [&](int c) {
        uint32_t stg = sbase + (uint32_t)(c & 1) * SSZ;
        int kc = c * 32;
        #pragma unroll
        for (int i = 0; i < 2; ++i) {
            int slot = i * 256 + tid, r = slot >> 2, sg = slot & 3;
            uint32_t so = r * STR + sg * 16;
            size_t go = (size_t)(m0 + r) * lda + kc + sg * 8;
            cpa16(stg + so, Ah + go);
            cpa16(stg + ALO + so, Al + go);
        }
        #pragma unroll
        for (int i = 0; i < BSEG; ++i) {
            int slot = i * 256 + tid, r = slot >> 2, sg = slot & 3;
            uint32_t so = r * STR + sg * 16;
            size_t go = (size_t)(n0 + r) * ldb + kc + sg * 8;
            cpa16(stg + BHO + so, Bh + go);
            cpa16(stg + BLO + so, Bl + go);
        }
        cpa_commit();
    };

    load_stage(0);
    uint32_t aAddr0 = sbase + (uint32_t)(wm + (lane & 15)) * STR + (lane >> 4) * 16;
    uint32_t bAddr0 = sbase + BHO + (uint32_t)(wn + (lane & 15)) * STR + (lane >> 4) * 16;

    for (int c = 0; c < NC; ++c) {
        cpa_wait0();
        __syncthreads();
        if (c + 1 < NC) load_stage(c + 1);
        uint32_t stg = (uint32_t)(c & 1) * SSZ;
        uint32_t aAddr = aAddr0 + stg, bAddr = bAddr0 + stg;
        #pragma unroll
        for (int ks = 0; ks < 2; ++ks) {
            // B fragments (hi+lo) and A-hi; A-lo reloaded later into same regs
            uint32_t a[4][4];
            uint32_t bh[NT8][2], bl[NT8][2];
            #pragma unroll
            for (int g = 0; g < NB16; ++g) {
                uint32_t base = bAddr + g * 16 * STR + ks * 32;
                uint32_t r0, r1, r2, r3;
                ldsm4(r0, r1, r2, r3, base);
                bh[2*g][0] = r0; bh[2*g][1] = r2;
                bh[2*g+1][0] = r1; bh[2*g+1][1] = r3;
                ldsm4(r0, r1, r2, r3, base + BN * STR);
                bl[2*g][0] = r0; bl[2*g][1] = r2;
                bl[2*g+1][0] = r1; bl[2*g+1][1] = r3;
            }
            #pragma unroll
            for (int mt = 0; mt < 4; ++mt) {
                uint32_t base = aAddr + mt * 16 * STR + ks * 32;
                ldsm4(a[mt][0], a[mt][1], a[mt][2], a[mt][3], base);
            }
            #pragma unroll
            for (int mt = 0; mt < 4; ++mt)
                #pragma unroll
                for (int n8 = 0; n8 < NT8; ++n8) {
                    mma16816(acc[mt][n8], a[mt], bh[n8]);
                    mma16816(acc[mt][n8], a[mt], bl[n8]);
                }
            #pragma unroll
            for (int mt = 0; mt < 4; ++mt) {
                uint32_t base = aAddr + ALO + mt * 16 * STR + ks * 32;
                ldsm4(a[mt][0], a[mt][1], a[mt][2], a[mt][3], base);
            }
            #pragma unroll
            for (int mt = 0; mt < 4; ++mt)
                #pragma unroll
                for (int n8 = 0; n8 < NT8; ++n8)
                    mma16816(acc[mt][n8], a[mt], bh[n8]);
        }
        // NOTE: no end-of-loop __syncthreads needed: next iteration's
        // wait+__syncthreads orders stage reuse (2-stage double buffer).
    }

    int gid = lane >> 2, tig = lane & 3;
    #pragma unroll
    for (int mt = 0; mt < 4; ++mt) {
        #pragma unroll
        for (int n8 = 0; n8 < NT8; ++n8) {
            int colb = n0 + wn + n8 * 8 + tig * 2;
            #pragma unroll
            for (int h2 = 0; h2 < 2; ++h2) {
                int m = m0 + wm + mt * 16 + gid + h2 * 8;
                #pragma unroll
                for (int cc = 0; cc < 2; ++cc) {
                    int n = colb + cc;
                    float v = acc[mt][n8][h2 * 2 + cc];
                    if (OMODE == 0) {
                        if (bias) v += bias[n];
                        if (resid) v += resid[(size_t)m * ldc + n];
                        if (relu) v = fmaxf(v, 0.f);
                        C[(size_t)m * ldc + n] = v;
                    } else if (OMODE == 1) {
                        C[(size_t)m * ldc + n] = v * 0.125f;
                    } else if (OMODE == 3) {
                        if (bias) v += bias[n];
                        if (relu) v = fmaxf(v, 0.f);
                        bf16 h, l; fsplit(v, h, l);
                        Ch[(size_t)m * ldc + n] = h;
                        Cl[(size_t)m * ldc + n] = l;
                    } else {  // OMODE 5
                        int b = m >> 10, t = m & 1023;
                        bf16 h, l; fsplit(v, h, l);
                        if (z < 2) {   // q, k: [bh][t][64]
                            size_t o = (size_t)(((b * 16 + (n >> 6)) << 10) + t) * 64 + (n & 63);
                            Ch[o] = h; Cl[o] = l;
                        } else {       // v: [bh][s][t]
                            size_t o = ((size_t)((b * 16 + (n >> 6)) * 64 + (n & 63)) << 10) + t;
                            Ch[o] = h; Cl[o] = l;
                        }
                    }
                }
            }
        }
    }
}

__global__ void embed_kernel(const int* __restrict__ idx,
                             const float* __restrict__ tok,
                             const float* __restrict__ pos) {
    size_t i = (size_t)blockIdx.x * 256 + threadIdx.x;
    int d  = (int)(i & (Dd - 1));
    int bt = (int)(i >> 10);
    int t  = bt & (Tt - 1);
    g_x[i] = tok[(size_t)idx[bt] * Dd + d] + pos[(size_t)t * Dd + d];
}

__global__ void ln_kernel(const float* __restrict__ x,
                          const float* __restrict__ g,
                          const float* __restrict__ b,
                          bf16* __restrict__ oh, bf16* __restrict__ ol) {
    __shared__ float s1[256], s2[256];
    int row = blockIdx.x;
    const float* xr = x + (size_t)row * Dd;
    int tid = threadIdx.x;
    float a = 0.f, a2 = 0.f;
    for (int i = tid; i < Dd; i += 256) { float v = xr[i]; a += v; a2 += v * v; }
    s1[tid] = a; s2[tid] = a2; __syncthreads();
    for (int s = 128; s > 0; s >>= 1) {
        if (tid < s) { s1[tid] += s1[tid + s]; s2[tid] += s2[tid + s]; }
        __syncthreads();
    }
    float mean = s1[0] * (1.f / Dd);
    float var  = s2[0] * (1.f / Dd) - mean * mean;
    float rstd = rsqrtf(var + EPSf);
    for (int i = tid; i < Dd; i += 256) {
        float v = (xr[i] - mean) * rstd * g[i] + b[i];
        bf16 h, l; fsplit(v, h, l);
        oh[(size_t)row * Dd + i] = h;
        ol[(size_t)row * Dd + i] = l;
    }
}

__global__ void softmax_kernel(float* __restrict__ attnL,
                               bf16* __restrict__ WH, bf16* __restrict__ WL) {
    __shared__ float sm[8];
    int rgl = blockIdx.x;
    int bh = rgl >> 10, t = rgl & (Tt - 1);
    size_t off = ((size_t)bh << 20) + ((size_t)t << 10);
    float* p = attnL + off;
    bf16* wh = WH + off;
    bf16* wl = WL + off;
    int tid = threadIdx.x, lane = tid & 31, wrp = tid >> 5;
    float v[4];
    float mx = -3.4e38f;
    #pragma unroll
    for (int k = 0; k < 4; ++k) {
        int i = k * 256 + tid;
        float x = p[i];
        v[k] = (i <= t) ? x : -3.4e38f;
        mx = fmaxf(mx, v[k]);
    }
    #pragma unroll
    for (int o = 16; o > 0; o >>= 1) mx = fmaxf(mx, __shfl_xor_sync(~0u, mx, o));
    if (lane == 0) sm[wrp] = mx;
    __syncthreads();
    mx = sm[0];
    #pragma unroll
    for (int w = 1; w < 8; ++w) mx = fmaxf(mx, sm[w]);
    float e[4], s = 0.f;
    #pragma unroll
    for (int k = 0; k < 4; ++k) {
        int i = k * 256 + tid;
        e[k] = (i <= t) ? __expf(v[k] - mx) : 0.f;
        s += e[k];
    }
    #pragma unroll
    for (int o = 16; o > 0; o >>= 1) s += __shfl_xor_sync(~0u, s, o);
    __syncthreads();
    if (lane == 0) sm[wrp] = s;
    __syncthreads();
    s = 0.f;
    #pragma unroll
    for (int w = 0; w < 8; ++w) s += sm[w];
    float inv = 1.f / s;
    #pragma unroll
    for (int k = 0; k < 4; ++k) {
        int i = k * 256 + tid;
        float r = e[k] * inv;
        p[i] = r;
        bf16 h, l; fsplit(r, h, l);
        wh[i] = h; wl[i] = l;
    }
}

__global__ void loss_row_kernel(const int* __restrict__ targets) {
    __shared__ float sd[256];
    int r = blockIdx.x;
    const float* p = g_logits + (size_t)r * Vv;
    int tid = threadIdx.x;
    float mx = -3.4e38f;
    for (int i = tid; i < Vv; i += 256) mx = fmaxf(mx, p[i]);
    sd[tid] = mx; __syncthreads();
    for (int s = 128; s > 0; s >>= 1) {
        if (tid < s) sd[tid] = fmaxf(sd[tid], sd[tid + s]);
        __syncthreads();
    }
    mx = sd[0]; __syncthreads();
    float sum = 0.f;
    for (int i = tid; i < Vv; i += 256) sum += __expf(p[i] - mx);
    sd[tid] = sum; __syncthreads();
    for (int s = 128; s > 0; s >>= 1) {
        if (tid < s) sd[tid] += sd[tid + s];
        __syncthreads();
    }
    if (tid == 0)
        g_rownll[r] = logf(sd[0]) + mx - p[targets[r]];
}

__global__ void loss_final_kernel(float* __restrict__ out) {
    __shared__ float sd[256];
    int tid = threadIdx.x;
    float s = 0.f;
    for (int i = tid; i < BT; i += 256) s += g_rownll[i];
    sd[tid] = s; __syncthreads();
    for (int st = 128; st > 0; st >>= 1) {
        if (tid < st) sd[tid] += sd[tid + st];
        __syncthreads();
    }
    if (tid == 0) out[0] = sd[0] * (1.f / BT);
}

#define SM128 (2 * ((256 + 2 * 128) * 80))
#define SM64  (2 * ((256 + 2 * 64) * 80))

extern "C" void kernel_launch(void* const* d_in, const int* in_sizes, int n_in,
                              void* d_out, int out_size) {
    (void)in_sizes; (void)n_in; (void)out_size;
    const int*   idx     = (const int*)d_in[0];
    const int*   targets = (const int*)d_in[1];
    const float* tok     = (const float*)d_in[2];
    const float* pos     = (const float*)d_in[3];
    const float* ln1_g   = (const float*)d_in[4];
    const float* ln1_b   = (const float*)d_in[5];
    const float* Wq      = (const float*)d_in[6];
    const float* Wk      = (const float*)d_in[7];
    const float* Wv      = (const float*)d_in[8];
    const float* Wp      = (const float*)d_in[9];
    const float* bp      = (const float*)d_in[10];
    const float* ln2_g   = (const float*)d_in[11];
    const float* ln2_b   = (const float*)d_in[12];
    const float* W1      = (const float*)d_in[13];
    const float* b1      = (const float*)d_in[14];
    const float* W2      = (const float*)d_in[15];
    const float* b2      = (const float*)d_in[16];
    const float* lnf_g   = (const float*)d_in[17];
    const float* lnf_b   = (const float*)d_in[18];
    const float* Wlm     = (const float*)d_in[19];
    const float* blm     = (const float*)d_in[20];

    float* out  = (float*)d_out;
    float* attn = out + 1;

    cudaFuncSetAttribute(gmma_kernel<128, 0>, cudaFuncAttributeMaxDynamicSharedMemorySize, SM128);
    cudaFuncSetAttribute(gmma_kernel<128, 1>, cudaFuncAttributeMaxDynamicSharedMemorySize, SM128);
    cudaFuncSetAttribute(gmma_kernel<128, 3>, cudaFuncAttributeMaxDynamicSharedMemorySize, SM128);
    cudaFuncSetAttribute(gmma_kernel<128, 5>, cudaFuncAttributeMaxDynamicSharedMemorySize, SM128);
    cudaFuncSetAttribute(gmma_kernel<64,  3>, cudaFuncAttributeMaxDynamicSharedMemorySize, SM64);

    float *px, *plog;
    cudaGetSymbolAddress((void**)&px,   g_x);
    cudaGetSymbolAddress((void**)&plog, g_logits);
    bf16 *hH,*hL,*qH,*qL,*kH,*kL,*vH,*vL,*oH,*oL,*fH,*fL,*wH,*wL;
    cudaGetSymbolAddress((void**)&hH, g_hH); cudaGetSymbolAddress((void**)&hL, g_hL);
    cudaGetSymbolAddress((void**)&qH, g_qH); cudaGetSymbolAddress((void**)&qL, g_qL);
    cudaGetSymbolAddress((void**)&kH, g_kH); cudaGetSymbolAddress((void**)&kL, g_kL);
    cudaGetSymbolAddress((void**)&vH, g_vH); cudaGetSymbolAddress((void**)&vL, g_vL);
    cudaGetSymbolAddress((void**)&oH, g_oH); cudaGetSymbolAddress((void**)&oL, g_oL);
    cudaGetSymbolAddress((void**)&fH, g_ffH); cudaGetSymbolAddress((void**)&fL, g_ffL);
    cudaGetSymbolAddress((void**)&wH, g_wH); cudaGetSymbolAddress((void**)&wL, g_wL);
    bf16 *wqh,*wql,*wkh,*wkl,*wvh,*wvl,*wph,*wpl,*w1h,*w1l,*w2h,*w2l,*wlh,*wll;
    cudaGetSymbolAddress((void**)&wqh, g_wqT_h); cudaGetSymbolAddress((void**)&wql, g_wqT_l);
    cudaGetSymbolAddress((void**)&wkh, g_wkT_h); cudaGetSymbolAddress((void**)&wkl, g_wkT_l);
    cudaGetSymbolAddress((void**)&wvh, g_wvT_h); cudaGetSymbolAddress((void**)&wvl, g_wvT_l);
    cudaGetSymbolAddress((void**)&wph, g_wpT_h); cudaGetSymbolAddress((void**)&wpl, g_wpT_l);
    cudaGetSymbolAddress((void**)&w1h, g_w1T_h); cudaGetSymbolAddress((void**)&w1l, g_w1T_l);
    cudaGetSymbolAddress((void**)&w2h, g_w2T_h); cudaGetSymbolAddress((void**)&w2l, g_w2T_l);
    cudaGetSymbolAddress((void**)&wlh, g_wlmT_h); cudaGetSymbolAddress((void**)&wll, g_wlmT_l);

    // two fused wsplit launches (also puts the scores GEMM at ncu launch #6)
    {
        WSDesc a0{Wq, wqh, wql, Dd, HSs, Ll*Hh};
        WSDesc a1{Wk, wkh, wkl, Dd, HSs, Ll*Hh};
        WSDesc a2{Wv, wvh, wvl, Dd, HSs, Ll*Hh};
        WSDesc a3{Wp, wph, wpl, Dd, Dd,  Ll};
        int nb0 = (HSs/32)*(Dd/32)*Ll*Hh, nb3 = (Dd/32)*(Dd/32)*Ll;
        wsplit_multi<<<nb0*3 + nb3, dim3(32, 8)>>>(a0, a1, a2, a3, nb0, nb0, nb0, nb3);
        WSDesc b0{W1, w1h, w1l, Dd, FFf, Ll};
        WSDesc b1{W2, w2h, w2l, FFf, Dd, Ll};
        WSDesc b2{Wlm, wlh, wll, Dd, Vv, 1};
        WSDesc b3{Wlm, wlh, wll, Dd, Vv, 0};   // unused slot
        int m0n = (FFf/32)*(Dd/32)*Ll, m1n = (Dd/32)*(FFf/32)*Ll, m2n = (Vv/32)*(Dd/32);
        wsplit_multi<<<m0n + m1n + m2n, dim3(32, 8)>>>(b0, b1, b2, b3, m0n, m1n, m2n, 0);
    }

    embed_kernel<<<BT * Dd / 256, 256>>>(idx, tok, pos);

    QKVP qpz{};  // zero for non-QKV launches
    const size_t WQL = (size_t)Hh * HSs * Dd;
    for (int l = 0; l < Ll; ++l) {
        float* attnL = attn + (size_t)l * Bb * Hh * Tt * Tt;

        ln_kernel<<<BT, 256>>>(px, ln1_g + (size_t)l * Dd, ln1_b + (size_t)l * Dd, hH, hL);

        // fused q/k/v
        QKVP qp{wqh + l * WQL, wql + l * WQL,
                wkh + l * WQL, wkl + l * WQL,
                wvh + l * WQL, wvl + l * WQL,
                qH, qL, kH, kL, vH, vL};
        gmma_kernel<128, 5><<<dim3(32, 8, 3), 256, SM128>>>(
            hH, hL, nullptr, nullptr, nullptr, nullptr, nullptr,
            nullptr, nullptr, 0, Dd, Dd, Dd, Dd, 0, 0, 0, 0, 0, 0, qp);

        // scores: A=q [bh][t][64], B=k [bh][t][64], C=attnL fp32
        gmma_kernel<128, 1><<<dim3(8, 8, Bb * Hh), 256, SM128>>>(
            qH, qL, kH, kL, attnL, nullptr, nullptr, nullptr, nullptr, 0,
            HSs, HSs, HSs, Tt,
            (size_t)16 * Tt * HSs, (size_t)Tt * HSs,
            (size_t)16 * Tt * HSs, (size_t)Tt * HSs,
            (size_t)16 * Tt * Tt, (size_t)Tt * Tt, qpz);

        softmax_kernel<<<Bb * Hh * Tt, 256>>>(attnL, wH, wL);

        gmma_kernel<64, 3><<<dim3(8, 1, Bb * Hh), 256, SM64>>>(
            wH, wL, vH, vL, nullptr, oH, oL, nullptr, nullptr, 0,
            Tt, Tt, Tt, Dd,
            (size_t)16 * Tt * Tt, (size_t)Tt * Tt,
            (size_t)16 * HSs * Tt, (size_t)HSs * Tt,
            (size_t)Tt * Dd, HSs, qpz);

        gmma_kernel<128, 0><<<dim3(32, 8, 1), 256, SM128>>>(
            oH, oL, wph + (size_t)l * Dd * Dd, wpl + (size_t)l * Dd * Dd,
            px, nullptr, nullptr, bp + (size_t)l * Dd, px, 0,
            Dd, Dd, Dd, Dd, 0, 0, 0, 0, 0, 0, qpz);

        ln_kernel<<<BT, 256>>>(px, ln2_g + (size_t)l * Dd, ln2_b + (size_t)l * Dd, hH, hL);

        gmma_kernel<128, 3><<<dim3(32, 32, 1), 256, SM128>>>(
            hH, hL, w1h + (size_t)l * Dd * FFf, w1l + (size_t)l * Dd * FFf,
            nullptr, fH, fL, b1 + (size_t)l * FFf, nullptr, 1,
            Dd, Dd, Dd, FFf, 0, 0, 0, 0, 0, 0, qpz);

        gmma_kernel<128, 0><<<dim3(32, 8, 1), 256, SM128>>>(
            fH, fL, w2h + (size_t)l * FFf * Dd, w2l + (size_t)l * FFf * Dd,
            px, nullptr, nullptr, b2 + (size_t)l * Dd, px, 0,
            FFf, FFf, FFf, Dd, 0, 0, 0, 0, 0, 0, qpz);
    }

    ln_kernel<<<BT, 256>>>(px, lnf_g, lnf_b, hH, hL);

    gmma_kernel<128, 0><<<dim3(32, 250, 1), 256, SM128>>>(
        hH, hL, wlh, wll, plog, nullptr, nullptr, blm, nullptr, 0,
        Dd, Dd, Dd, Vv, 0, 0, 0, 0, 0, 0, qpz);

    loss_row_kernel<<<BT, 256>>>(targets);
    loss_final_kernel<<<1, 256>>>(out);
}

// round 9
// speedup vs baseline: 2.5118x; 1.0952x over previous
#include <cuda_runtime.h>
#include <cuda_bf16.h>
#include <math.h>
#include <stdint.h>

#define Bb   4
#define Tt   1024
#define Dd   1024
#define Hh   16
#define HSs  64
#define Ll   4
#define FFf  4096
#define Vv   32000
#define BT   (Bb*Tt)
#define EPSf 1e-5f

typedef __nv_bfloat16 bf16;

__device__ float g_x[BT*Dd];
__device__ float g_logits[(size_t)BT*Vv];
__device__ float g_rownll[BT];
__device__ __align__(16) bf16 g_hH[BT*Dd],  g_hL[BT*Dd];
__device__ __align__(16) bf16 g_qH[BT*Dd],  g_qL[BT*Dd];
__device__ __align__(16) bf16 g_kH[BT*Dd],  g_kL[BT*Dd];
__device__ __align__(16) bf16 g_vH[BT*Dd],  g_vL[BT*Dd];
__device__ __align__(16) bf16 g_oH[BT*Dd],  g_oL[BT*Dd];
__device__ __align__(16) bf16 g_ffH[(size_t)BT*FFf], g_ffL[(size_t)BT*FFf];
__device__ __align__(16) bf16 g_wH[(size_t)Bb*Hh*Tt*Tt], g_wL[(size_t)Bb*Hh*Tt*Tt];
__device__ __align__(16) bf16 g_wqT_h[Ll*Hh*HSs*Dd], g_wqT_l[Ll*Hh*HSs*Dd];
__device__ __align__(16) bf16 g_wkT_h[Ll*Hh*HSs*Dd], g_wkT_l[Ll*Hh*HSs*Dd];
__device__ __align__(16) bf16 g_wvT_h[Ll*Hh*HSs*Dd], g_wvT_l[Ll*Hh*HSs*Dd];
__device__ __align__(16) bf16 g_wpT_h[(size_t)Ll*Dd*Dd], g_wpT_l[(size_t)Ll*Dd*Dd];
__device__ __align__(16) bf16 g_w1T_h[(size_t)Ll*FFf*Dd], g_w1T_l[(size_t)Ll*FFf*Dd];
__device__ __align__(16) bf16 g_w2T_h[(size_t)Ll*Dd*FFf], g_w2T_l[(size_t)Ll*Dd*FFf];
__device__ __align__(16) bf16 g_wlmT_h[(size_t)Vv*Dd];

__device__ __forceinline__ uint32_t smem_u32(const void* p) {
    uint32_t a;
    asm("{ .reg .u64 t; cvta.to.shared.u64 t, %1; cvt.u32.u64 %0, t; }" : "=r"(a) : "l"(p));
    return a;
}
__device__ __forceinline__ void ldsm4(uint32_t& r0, uint32_t& r1, uint32_t& r2,
                                      uint32_t& r3, uint32_t addr) {
    asm volatile("ldmatrix.sync.aligned.m8n8.x4.shared.b16 {%0,%1,%2,%3}, [%4];"
                 : "=r"(r0), "=r"(r1), "=r"(r2), "=r"(r3) : "r"(addr));
}
__device__ __forceinline__ void mma16816(float* c, const uint32_t* a, const uint32_t* b) {
    asm volatile(
        "mma.sync.aligned.m16n8k16.row.col.f32.bf16.bf16.f32 "
        "{%0,%1,%2,%3}, {%4,%5,%6,%7}, {%8,%9}, {%0,%1,%2,%3};"
        : "+f"(c[0]), "+f"(c[1]), "+f"(c[2]), "+f"(c[3])
        : "r"(a[0]), "r"(a[1]), "r"(a[2]), "r"(a[3]), "r"(b[0]), "r"(b[1]));
}
__device__ __forceinline__ void cpa16(uint32_t s, const void* g) {
    asm volatile("cp.async.cg.shared.global [%0], [%1], 16;" :: "r"(s), "l"(g));
}
__device__ __forceinline__ void cpa_commit() {
    asm volatile("cp.async.commit_group;" ::: "memory");
}
__device__ __forceinline__ void cpa_wait0() {
    asm volatile("cp.async.wait_group 0;" ::: "memory");
}
__device__ __forceinline__ void fsplit(float v, bf16& h, bf16& l) {
    h = __float2bfloat16(v);
    l = __float2bfloat16(v - __bfloat162float(h));
}

// ---------------- fused weight transpose + split (up to 4 weights) ----------
struct WSDesc { const float* W; bf16* H; bf16* L; int R, C, nz; };

__global__ void wsplit_multi(WSDesc d0, WSDesc d1, WSDesc d2, WSDesc d3,
                             int nb0, int nb1, int nb2, int nb3) {
    __shared__ float ts[32][33];
    int id = blockIdx.x;
    WSDesc d;
    if (id < nb0) { d = d0; }
    else if (id < nb0 + nb1) { d = d1; id -= nb0; }
    else if (id < nb0 + nb1 + nb2) { d = d2; id -= nb0 + nb1; }
    else { d = d3; id -= nb0 + nb1 + nb2; }
    int nbx = d.C >> 5, nby = d.R >> 5;
    int z = id / (nbx * nby);
    int rem = id - z * nbx * nby;
    int by = rem / nbx, bx = rem - by * nbx;
    size_t mo = (size_t)z * d.R * d.C;
    int c0 = bx * 32, r0 = by * 32;
    int tx = threadIdx.x, ty = threadIdx.y;
    #pragma unroll
    for (int i = 0; i < 4; ++i) {
        int r = r0 + ty + i * 8;
        ts[ty + i * 8][tx] = d.W[mo + (size_t)r * d.C + c0 + tx];
    }
    __syncthreads();
    #pragma unroll
    for (int i = 0; i < 4; ++i) {
        int n = c0 + ty + i * 8;
        int k = r0 + tx;
        float v = ts[tx][ty + i * 8];
        bf16 h = __float2bfloat16(v);
        d.H[mo + (size_t)n * d.R + k] = h;
        if (d.L)
            d.L[mo + (size_t)n * d.R + k] = __float2bfloat16(v - __bfloat162float(h));
    }
}

// ---------------- unified bf16 hi/lo tensor-core GEMM -----------------------
// OMODE 0: fp32 +bias/resid/relu | 1: scores | 3: bf16 linear | 5: fused QKV
// NPROD 3: ah*bh + ah*bl + al*bh | NPROD 2: ah*bh + al*bh (skip B-lo entirely)
// KCAUS: truncate K to (blockIdx.x+1)*128 (attn·V; wei is causal-zero beyond)
struct QKVP {
    const bf16 *bh0, *bl0, *bh1, *bl1, *bh2, *bl2;
    bf16 *ch0, *cl0, *ch1, *cl1, *ch2, *cl2;
};

template<int BN, int OMODE, int NPROD, bool KCAUS>
__global__ __launch_bounds__(256, 2)
void gmma_kernel(const bf16* __restrict__ Ah, const bf16* __restrict__ Al,
                 const bf16* __restrict__ Bhp, const bf16* __restrict__ Blp,
                 float* __restrict__ C, bf16* __restrict__ Chp, bf16* __restrict__ Clp,
                 const float* __restrict__ bias, const float* __restrict__ resid,
                 int relu, int K, int lda, int ldb, int ldc,
                 size_t aZh, size_t aZl, size_t bZh, size_t bZl,
                 size_t cZh, size_t cZl, QKVP qp) {
    constexpr int STR = 80;
    constexpr int ALO = 128 * STR;
    constexpr int BHO = 256 * STR;
    constexpr int BLO = BHO + BN * STR;
    constexpr int SSZ = BHO + 2 * BN * STR;
    constexpr int NT8 = BN / 32;
    constexpr int NB16 = NT8 / 2;
    constexpr int BSEG = BN * 4 / 256;
    extern __shared__ __align__(16) unsigned char smem[];

    int m0 = blockIdx.x * 128, n0 = blockIdx.y * BN;
    if (OMODE == 1 && n0 > m0) return;
    int z = blockIdx.z;
    const bf16 *Bh, *Bl = nullptr;
    bf16 *Ch = nullptr, *Cl = nullptr;
    if (OMODE == 5) {
        if (z == 0)      { Bh = qp.bh0; Bl = qp.bl0; Ch = qp.ch0; Cl = qp.cl0; }
        else if (z == 1) { Bh = qp.bh1; Bl = qp.bl1; Ch = qp.ch1; Cl = qp.cl1; }
        else             { Bh = qp.bh2; Bl = qp.bl2; Ch = qp.ch2; Cl = qp.cl2; }
    } else {
        Ah += (size_t)(z >> 4) * aZh + (size_t)(z & 15) * aZl;
        Al += (size_t)(z >> 4) * aZh + (size_t)(z & 15) * aZl;
        Bh = Bhp + (size_t)(z >> 4) * bZh + (size_t)(z & 15) * bZl;
        if (NPROD == 3) Bl = Blp + (size_t)(z >> 4) * bZh + (size_t)(z & 15) * bZl;
        if (OMODE == 0 || OMODE == 1)
            C += (size_t)(z >> 4) * cZh + (size_t)(z & 15) * cZl;
        else {
            Ch = Chp + (size_t)(z >> 4) * cZh + (size_t)(z & 15) * cZl;
            Cl = Clp + (size_t)(z >> 4) * cZh + (size_t)(z & 15) * cZl;
        }
    }

    int tid = threadIdx.x, lane = tid & 31, wid = tid >> 5;
    int wm = (wid & 1) * 64;
    int wn = (wid >> 1) * (BN / 4);

    float acc[4][NT8][4];
    #pragma unroll
    for (int i = 0; i < 4; ++i)
        #pragma unroll
        for (int j = 0; j < NT8; ++j)
            #pragma unroll
            for (int q = 0; q < 4; ++q) acc[i][j][q] = 0.f;

    uint32_t sbase = smem_u32(smem);
    int NC = KCAUS ? (blockIdx.x + 1) * 4 : (K / 32);

    auto load_stage = [&](int c) {
        uint32_t stg = sbase + (uint32_t)(c & 1) * SSZ;
        int kc = c * 32;
        #pragma unroll
        for (int i = 0; i < 2; ++i) {
            int slot = i * 256 + tid, r = slot >> 2, sg = slot & 3;
            uint32_t so = r * STR + sg * 16;
            size_t go = (size_t)(m0 + r) * lda + kc + sg * 8;
            cpa16(stg + so, Ah + go);
            cpa16(stg + ALO + so, Al + go);
        }
        #pragma unroll
        for (int i = 0; i < BSEG; ++i) {
            int slot = i * 256 + tid, r = slot >> 2, sg = slot & 3;
            uint32_t so = r * STR + sg * 16;
            size_t go = (size_t)(n0 + r) * ldb + kc + sg * 8;
            cpa16(stg + BHO + so, Bh + go);
            if (NPROD == 3) cpa16(stg + BLO + so, Bl + go);
        }
        cpa_commit();
    };

    load_stage(0);
    uint32_t aAddr0 = sbase + (uint32_t)(wm + (lane & 15)) * STR + (lane >> 4) * 16;
    uint32_t bAddr0 = sbase + BHO + (uint32_t)(wn + (lane & 15)) * STR + (lane >> 4) * 16;

    for (int c = 0; c < NC; ++c) {
        cpa_wait0();
        __syncthreads();
        if (c + 1 < NC) load_stage(c + 1);
        uint32_t stg = (uint32_t)(c & 1) * SSZ;
        uint32_t aAddr = aAddr0 + stg, bAddr = bAddr0 + stg;
        #pragma unroll
        for (int ks = 0; ks < 2; ++ks) {
            uint32_t a[4][4];
            uint32_t bh[NT8][2], bl[NT8][2];
            #pragma unroll
            for (int g = 0; g < NB16; ++g) {
                uint32_t base = bAddr + g * 16 * STR + ks * 32;
                uint32_t r0, r1, r2, r3;
                ldsm4(r0, r1, r2, r3, base);
                bh[2*g][0] = r0; bh[2*g][1] = r2;
                bh[2*g+1][0] = r1; bh[2*g+1][1] = r3;
                if (NPROD == 3) {
                    ldsm4(r0, r1, r2, r3, base + BN * STR);
                    bl[2*g][0] = r0; bl[2*g][1] = r2;
                    bl[2*g+1][0] = r1; bl[2*g+1][1] = r3;
                }
            }
            #pragma unroll
            for (int mt = 0; mt < 4; ++mt) {
                uint32_t base = aAddr + mt * 16 * STR + ks * 32;
                ldsm4(a[mt][0], a[mt][1], a[mt][2], a[mt][3], base);
            }
            #pragma unroll
            for (int mt = 0; mt < 4; ++mt)
                #pragma unroll
                for (int n8 = 0; n8 < NT8; ++n8) {
                    mma16816(acc[mt][n8], a[mt], bh[n8]);
                    if (NPROD == 3) mma16816(acc[mt][n8], a[mt], bl[n8]);
                }
            #pragma unroll
            for (int mt = 0; mt < 4; ++mt) {
                uint32_t base = aAddr + ALO + mt * 16 * STR + ks * 32;
                ldsm4(a[mt][0], a[mt][1], a[mt][2], a[mt][3], base);
            }
            #pragma unroll
            for (int mt = 0; mt < 4; ++mt)
                #pragma unroll
                for (int n8 = 0; n8 < NT8; ++n8)
                    mma16816(acc[mt][n8], a[mt], bh[n8]);
        }
    }

    int gid = lane >> 2, tig = lane & 3;
    #pragma unroll
    for (int mt = 0; mt < 4; ++mt) {
        #pragma unroll
        for (int n8 = 0; n8 < NT8; ++n8) {
            int colb = n0 + wn + n8 * 8 + tig * 2;
            #pragma unroll
            for (int h2 = 0; h2 < 2; ++h2) {
                int m = m0 + wm + mt * 16 + gid + h2 * 8;
                #pragma unroll
                for (int cc = 0; cc < 2; ++cc) {
                    int n = colb + cc;
                    float v = acc[mt][n8][h2 * 2 + cc];
                    if (OMODE == 0) {
                        if (bias) v += bias[n];
                        if (resid) v += resid[(size_t)m * ldc + n];
                        if (relu) v = fmaxf(v, 0.f);
                        C[(size_t)m * ldc + n] = v;
                    } else if (OMODE == 1) {
                        C[(size_t)m * ldc + n] = v * 0.125f;
                    } else if (OMODE == 3) {
                        if (bias) v += bias[n];
                        if (relu) v = fmaxf(v, 0.f);
                        bf16 h, l; fsplit(v, h, l);
                        Ch[(size_t)m * ldc + n] = h;
                        Cl[(size_t)m * ldc + n] = l;
                    } else {  // OMODE 5
                        int b = m >> 10, t = m & 1023;
                        bf16 h, l; fsplit(v, h, l);
                        if (z < 2) {   // q, k: [bh][t][64]
                            size_t o = (size_t)(((b * 16 + (n >> 6)) << 10) + t) * 64 + (n & 63);
                            Ch[o] = h; Cl[o] = l;
                        } else {       // v: [bh][s][t]
                            size_t o = ((size_t)((b * 16 + (n >> 6)) * 64 + (n & 63)) << 10) + t;
                            Ch[o] = h; Cl[o] = l;
                        }
                    }
                }
            }
        }
    }
}

__global__ void embed_kernel(const int* __restrict__ idx,
                             const float* __restrict__ tok,
                             const float* __restrict__ pos) {
    size_t i = (size_t)blockIdx.x * 256 + threadIdx.x;
    int d  = (int)(i & (Dd - 1));
    int bt = (int)(i >> 10);
    int t  = bt & (Tt - 1);
    g_x[i] = tok[(size_t)idx[bt] * Dd + d] + pos[(size_t)t * Dd + d];
}

__global__ void ln_kernel(const float* __restrict__ x,
                          const float* __restrict__ g,
                          const float* __restrict__ b,
                          bf16* __restrict__ oh, bf16* __restrict__ ol) {
    __shared__ float s1[256], s2[256];
    int row = blockIdx.x;
    const float* xr = x + (size_t)row * Dd;
    int tid = threadIdx.x;
    float a = 0.f, a2 = 0.f;
    for (int i = tid; i < Dd; i += 256) { float v = xr[i]; a += v; a2 += v * v; }
    s1[tid] = a; s2[tid] = a2; __syncthreads();
    for (int s = 128; s > 0; s >>= 1) {
        if (tid < s) { s1[tid] += s1[tid + s]; s2[tid] += s2[tid + s]; }
        __syncthreads();
    }
    float mean = s1[0] * (1.f / Dd);
    float var  = s2[0] * (1.f / Dd) - mean * mean;
    float rstd = rsqrtf(var + EPSf);
    for (int i = tid; i < Dd; i += 256) {
        float v = (xr[i] - mean) * rstd * g[i] + b[i];
        bf16 h, l; fsplit(v, h, l);
        oh[(size_t)row * Dd + i] = h;
        ol[(size_t)row * Dd + i] = l;
    }
}

__global__ void softmax_kernel(float* __restrict__ attnL,
                               bf16* __restrict__ WH, bf16* __restrict__ WL) {
    __shared__ float sm[8];
    int rgl = blockIdx.x;
    int bh = rgl >> 10, t = rgl & (Tt - 1);
    size_t off = ((size_t)bh << 20) + ((size_t)t << 10);
    float* p = attnL + off;
    bf16* wh = WH + off;
    bf16* wl = WL + off;
    int tid = threadIdx.x, lane = tid & 31, wrp = tid >> 5;
    float v[4];
    float mx = -3.4e38f;
    #pragma unroll
    for (int k = 0; k < 4; ++k) {
        int i = k * 256 + tid;
        float x = p[i];
        v[k] = (i <= t) ? x : -3.4e38f;
        mx = fmaxf(mx, v[k]);
    }
    #pragma unroll
    for (int o = 16; o > 0; o >>= 1) mx = fmaxf(mx, __shfl_xor_sync(~0u, mx, o));
    if (lane == 0) sm[wrp] = mx;
    __syncthreads();
    mx = sm[0];
    #pragma unroll
    for (int w = 1; w < 8; ++w) mx = fmaxf(mx, sm[w]);
    float e[4], s = 0.f;
    #pragma unroll
    for (int k = 0; k < 4; ++k) {
        int i = k * 256 + tid;
        e[k] = (i <= t) ? __expf(v[k] - mx) : 0.f;
        s += e[k];
    }
    #pragma unroll
    for (int o = 16; o > 0; o >>= 1) s += __shfl_xor_sync(~0u, s, o);
    __syncthreads();
    if (lane == 0) sm[wrp] = s;
    __syncthreads();
    s = 0.f;
    #pragma unroll
    for (int w = 0; w < 8; ++w) s += sm[w];
    float inv = 1.f / s;
    #pragma unroll
    for (int k = 0; k < 4; ++k) {
        int i = k * 256 + tid;
        float r = e[k] * inv;
        p[i] = r;
        bf16 h, l; fsplit(r, h, l);
        wh[i] = h; wl[i] = l;
    }
}

__global__ void loss_row_kernel(const int* __restrict__ targets) {
    __shared__ float sd[256];
    int r = blockIdx.x;
    const float* p = g_logits + (size_t)r * Vv;
    int tid = threadIdx.x;
    float mx = -3.4e38f;
    for (int i = tid; i < Vv; i += 256) mx = fmaxf(mx, p[i]);
    sd[tid] = mx; __syncthreads();
    for (int s = 128; s > 0; s >>= 1) {
        if (tid < s) sd[tid] = fmaxf(sd[tid], sd[tid + s]);
        __syncthreads();
    }
    mx = sd[0]; __syncthreads();
    float sum = 0.f;
    for (int i = tid; i < Vv; i += 256) sum += __expf(p[i] - mx);
    sd[tid] = sum; __syncthreads();
    for (int s = 128; s > 0; s >>= 1) {
        if (tid < s) sd[tid] += sd[tid + s];
        __syncthreads();
    }
    if (tid == 0)
        g_rownll[r] = logf(sd[0]) + mx - p[targets[r]];
}

__global__ void loss_final_kernel(float* __restrict__ out) {
    __shared__ float sd[256];
    int tid = threadIdx.x;
    float s = 0.f;
    for (int i = tid; i < BT; i += 256) s += g_rownll[i];
    sd[tid] = s; __syncthreads();
    for (int st = 128; st > 0; st >>= 1) {
        if (tid < st) sd[tid] += sd[tid + st];
        __syncthreads();
    }
    if (tid == 0) out[0] = sd[0] * (1.f / BT);
}

#define SM128 (2 * ((256 + 2 * 128) * 80))
#define SM64  (2 * ((256 + 2 * 64) * 80))

extern "C" void kernel_launch(void* const* d_in, const int* in_sizes, int n_in,
                              void* d_out, int out_size) {
    (void)in_sizes; (void)n_in; (void)out_size;
    const int*   idx     = (const int*)d_in[0];
    const int*   targets = (const int*)d_in[1];
    const float* tok     = (const float*)d_in[2];
    const float* pos     = (const float*)d_in[3];
    const float* ln1_g   = (const float*)d_in[4];
    const float* ln1_b   = (const float*)d_in[5];
    const float* Wq      = (const float*)d_in[6];
    const float* Wk      = (const float*)d_in[7];
    const float* Wv      = (const float*)d_in[8];
    const float* Wp      = (const float*)d_in[9];
    const float* bp      = (const float*)d_in[10];
    const float* ln2_g   = (const float*)d_in[11];
    const float* ln2_b   = (const float*)d_in[12];
    const float* W1      = (const float*)d_in[13];
    const float* b1      = (const float*)d_in[14];
    const float* W2      = (const float*)d_in[15];
    const float* b2      = (const float*)d_in[16];
    const float* lnf_g   = (const float*)d_in[17];
    const float* lnf_b   = (const float*)d_in[18];
    const float* Wlm     = (const float*)d_in[19];
    const float* blm     = (const float*)d_in[20];

    float* out  = (float*)d_out;
    float* attn = out + 1;

    cudaFuncSetAttribute(gmma_kernel<128, 0, 3, false>, cudaFuncAttributeMaxDynamicSharedMemorySize, SM128);
    cudaFuncSetAttribute(gmma_kernel<128, 0, 2, false>, cudaFuncAttributeMaxDynamicSharedMemorySize, SM128);
    cudaFuncSetAttribute(gmma_kernel<128, 1, 3, false>, cudaFuncAttributeMaxDynamicSharedMemorySize, SM128);
    cudaFuncSetAttribute(gmma_kernel<128, 3, 3, false>, cudaFuncAttributeMaxDynamicSharedMemorySize, SM128);
    cudaFuncSetAttribute(gmma_kernel<128, 5, 3, false>, cudaFuncAttributeMaxDynamicSharedMemorySize, SM128);
    cudaFuncSetAttribute(gmma_kernel<64,  3, 3, true >, cudaFuncAttributeMaxDynamicSharedMemorySize, SM64);

    float *px, *plog;
    cudaGetSymbolAddress((void**)&px,   g_x);
    cudaGetSymbolAddress((void**)&plog, g_logits);
    bf16 *hH,*hL,*qH,*qL,*kH,*kL,*vH,*vL,*oH,*oL,*fH,*fL,*wH,*wL;
    cudaGetSymbolAddress((void**)&hH, g_hH); cudaGetSymbolAddress((void**)&hL, g_hL);
    cudaGetSymbolAddress((void**)&qH, g_qH); cudaGetSymbolAddress((void**)&qL, g_qL);
    cudaGetSymbolAddress((void**)&kH, g_kH); cudaGetSymbolAddress((void**)&kL, g_kL);
    cudaGetSymbolAddress((void**)&vH, g_vH); cudaGetSymbolAddress((void**)&vL, g_vL);
    cudaGetSymbolAddress((void**)&oH, g_oH); cudaGetSymbolAddress((void**)&oL, g_oL);
    cudaGetSymbolAddress((void**)&fH, g_ffH); cudaGetSymbolAddress((void**)&fL, g_ffL);
    cudaGetSymbolAddress((void**)&wH, g_wH); cudaGetSymbolAddress((void**)&wL, g_wL);
    bf16 *wqh,*wql,*wkh,*wkl,*wvh,*wvl,*wph,*wpl,*w1h,*w1l,*w2h,*w2l,*wlh;
    cudaGetSymbolAddress((void**)&wqh, g_wqT_h); cudaGetSymbolAddress((void**)&wql, g_wqT_l);
    cudaGetSymbolAddress((void**)&wkh, g_wkT_h); cudaGetSymbolAddress((void**)&wkl, g_wkT_l);
    cudaGetSymbolAddress((void**)&wvh, g_wvT_h); cudaGetSymbolAddress((void**)&wvl, g_wvT_l);
    cudaGetSymbolAddress((void**)&wph, g_wpT_h); cudaGetSymbolAddress((void**)&wpl, g_wpT_l);
    cudaGetSymbolAddress((void**)&w1h, g_w1T_h); cudaGetSymbolAddress((void**)&w1l, g_w1T_l);
    cudaGetSymbolAddress((void**)&w2h, g_w2T_h); cudaGetSymbolAddress((void**)&w2l, g_w2T_l);
    cudaGetSymbolAddress((void**)&wlh, g_wlmT_h);

    {
        WSDesc a0{Wq, wqh, wql, Dd, HSs, Ll*Hh};
        WSDesc a1{Wk, wkh, wkl, Dd, HSs, Ll*Hh};
        WSDesc a2{Wv, wvh, wvl, Dd, HSs, Ll*Hh};
        WSDesc a3{Wp, wph, wpl, Dd, Dd,  Ll};
        int nb0 = (HSs/32)*(Dd/32)*Ll*Hh, nb3 = (Dd/32)*(Dd/32)*Ll;
        wsplit_multi<<<nb0*3 + nb3, dim3(32, 8)>>>(a0, a1, a2, a3, nb0, nb0, nb0, nb3);
        WSDesc b0{W1, w1h, w1l, Dd, FFf, Ll};
        WSDesc b1{W2, w2h, w2l, FFf, Dd, Ll};
        WSDesc b2{Wlm, wlh, nullptr, Dd, Vv, 1};   // head is 2-product: no lo
        WSDesc b3{Wlm, wlh, nullptr, Dd, Vv, 0};
        int m0n = (FFf/32)*(Dd/32)*Ll, m1n = (Dd/32)*(FFf/32)*Ll, m2n = (Vv/32)*(Dd/32);
        wsplit_multi<<<m0n + m1n + m2n, dim3(32, 8)>>>(b0, b1, b2, b3, m0n, m1n, m2n, 0);
    }

    embed_kernel<<<BT * Dd / 256, 256>>>(idx, tok, pos);

    QKVP qpz{};
    const size_t WQL = (size_t)Hh * HSs * Dd;
    for (int l = 0; l < Ll; ++l) {
        float* attnL = attn + (size_t)l * Bb * Hh * Tt * Tt;

        ln_kernel<<<BT, 256>>>(px, ln1_g + (size_t)l * Dd, ln1_b + (size_t)l * Dd, hH, hL);

        QKVP qp{wqh + l * WQL, wql + l * WQL,
                wkh + l * WQL, wkl + l * WQL,
                wvh + l * WQL, wvl + l * WQL,
                qH, qL, kH, kL, vH, vL};
        gmma_kernel<128, 5, 3, false><<<dim3(32, 8, 3), 256, SM128>>>(
            hH, hL, nullptr, nullptr, nullptr, nullptr, nullptr,
            nullptr, nullptr, 0, Dd, Dd, Dd, Dd, 0, 0, 0, 0, 0, 0, qp);

        gmma_kernel<128, 1, 3, false><<<dim3(8, 8, Bb * Hh), 256, SM128>>>(
            qH, qL, kH, kL, attnL, nullptr, nullptr, nullptr, nullptr, 0,
            HSs, HSs, HSs, Tt,
            (size_t)16 * Tt * HSs, (size_t)Tt * HSs,
            (size_t)16 * Tt * HSs, (size_t)Tt * HSs,
            (size_t)16 * Tt * Tt, (size_t)Tt * Tt, qpz);

        softmax_kernel<<<Bb * Hh * Tt, 256>>>(attnL, wH, wL);

        // attn·V with causal K truncation (exact: wei zero beyond row index)
        gmma_kernel<64, 3, 3, true><<<dim3(8, 1, Bb * Hh), 256, SM64>>>(
            wH, wL, vH, vL, nullptr, oH, oL, nullptr, nullptr, 0,
            Tt, Tt, Tt, Dd,
            (size_t)16 * Tt * Tt, (size_t)Tt * Tt,
            (size_t)16 * HSs * Tt, (size_t)HSs * Tt,
            (size_t)Tt * Dd, HSs, qpz);

        gmma_kernel<128, 0, 3, false><<<dim3(32, 8, 1), 256, SM128>>>(
            oH, oL, wph + (size_t)l * Dd * Dd, wpl + (size_t)l * Dd * Dd,
            px, nullptr, nullptr, bp + (size_t)l * Dd, px, 0,
            Dd, Dd, Dd, Dd, 0, 0, 0, 0, 0, 0, qpz);

        ln_kernel<<<BT, 256>>>(px, ln2_g + (size_t)l * Dd, ln2_b + (size_t)l * Dd, hH, hL);

        gmma_kernel<128, 3, 3, false><<<dim3(32, 32, 1), 256, SM128>>>(
            hH, hL, w1h + (size_t)l * Dd * FFf, w1l + (size_t)l * Dd * FFf,
            nullptr, fH, fL, b1 + (size_t)l * FFf, nullptr, 1,
            Dd, Dd, Dd, FFf, 0, 0, 0, 0, 0, 0, qpz);

        gmma_kernel<128, 0, 3, false><<<dim3(32, 8, 1), 256, SM128>>>(
            fH, fL, w2h + (size_t)l * FFf * Dd, w2l + (size_t)l * FFf * Dd,
            px, nullptr, nullptr, b2 + (size_t)l * Dd, px, 0,
            FFf, FFf, FFf, Dd, 0, 0, 0, 0, 0, 0, qpz);
    }

    ln_kernel<<<BT, 256>>>(px, lnf_g, lnf_b, hH, hL);

    // LM head: 2-product (exact activations x bf16 weights) — loss-only path
    gmma_kernel<128, 0, 2, false><<<dim3(32, 250, 1), 256, SM128>>>(
        hH, hL, wlh, nullptr, plog, nullptr, nullptr, blm, nullptr, 0,
        Dd, Dd, Dd, Vv, 0, 0, 0, 0, 0, 0, qpz);

    loss_row_kernel<<<BT, 256>>>(targets);
    loss_final_kernel<<<1, 256>>>(out);
}

// round 10
// speedup vs baseline: 2.7994x; 1.1145x over previous
#include <cuda_runtime.h>
#include <cuda_bf16.h>
#include <math.h>
#include <stdint.h>

#define Bb   4
#define Tt   1024
#define Dd   1024
#define Hh   16
#define HSs  64
#define Ll   4
#define FFf  4096
#define Vv   32000
#define BT   (Bb*Tt)
#define EPSf 1e-5f

typedef __nv_bfloat16 bf16;

__device__ float g_x[BT*Dd];
__device__ float g_logits[(size_t)BT*Vv];
__device__ float g_rownll[BT];
__device__ __align__(16) bf16 g_hH[BT*Dd],  g_hL[BT*Dd];
__device__ __align__(16) bf16 g_qH[BT*Dd],  g_qL[BT*Dd];
__device__ __align__(16) bf16 g_kH[BT*Dd],  g_kL[BT*Dd];
__device__ __align__(16) bf16 g_vH[BT*Dd],  g_vL[BT*Dd];
__device__ __align__(16) bf16 g_oH[BT*Dd],  g_oL[BT*Dd];
__device__ __align__(16) bf16 g_ffH[(size_t)BT*FFf], g_ffL[(size_t)BT*FFf];
__device__ __align__(16) bf16 g_wH[(size_t)Bb*Hh*Tt*Tt], g_wL[(size_t)Bb*Hh*Tt*Tt];
__device__ __align__(16) bf16 g_wqT_h[Ll*Hh*HSs*Dd], g_wqT_l[Ll*Hh*HSs*Dd];
__device__ __align__(16) bf16 g_wkT_h[Ll*Hh*HSs*Dd], g_wkT_l[Ll*Hh*HSs*Dd];
__device__ __align__(16) bf16 g_wvT_h[Ll*Hh*HSs*Dd], g_wvT_l[Ll*Hh*HSs*Dd];
__device__ __align__(16) bf16 g_wpT_h[(size_t)Ll*Dd*Dd], g_wpT_l[(size_t)Ll*Dd*Dd];
__device__ __align__(16) bf16 g_w1T_h[(size_t)Ll*FFf*Dd], g_w1T_l[(size_t)Ll*FFf*Dd];
__device__ __align__(16) bf16 g_w2T_h[(size_t)Ll*Dd*FFf], g_w2T_l[(size_t)Ll*Dd*FFf];
__device__ __align__(16) bf16 g_wlmT_h[(size_t)Vv*Dd];

__device__ __forceinline__ uint32_t smem_u32(const void* p) {
    uint32_t a;
    asm("{ .reg .u64 t; cvta.to.shared.u64 t, %1; cvt.u32.u64 %0, t; }" : "=r"(a) : "l"(p));
    return a;
}
__device__ __forceinline__ void ldsm4(uint32_t& r0, uint32_t& r1, uint32_t& r2,
                                      uint32_t& r3, uint32_t addr) {
    asm volatile("ldmatrix.sync.aligned.m8n8.x4.shared.b16 {%0,%1,%2,%3}, [%4];"
                 : "=r"(r0), "=r"(r1), "=r"(r2), "=r"(r3) : "r"(addr));
}
__device__ __forceinline__ void mma16816(float* c, const uint32_t* a, const uint32_t* b) {
    asm volatile(
        "mma.sync.aligned.m16n8k16.row.col.f32.bf16.bf16.f32 "
        "{%0,%1,%2,%3}, {%4,%5,%6,%7}, {%8,%9}, {%0,%1,%2,%3};"
        : "+f"(c[0]), "+f"(c[1]), "+f"(c[2]), "+f"(c[3])
        : "r"(a[0]), "r"(a[1]), "r"(a[2]), "r"(a[3]), "r"(b[0]), "r"(b[1]));
}
__device__ __forceinline__ void cpa16(uint32_t s, const void* g) {
    asm volatile("cp.async.cg.shared.global [%0], [%1], 16;" :: "r"(s), "l"(g));
}
__device__ __forceinline__ void cpa_commit() {
    asm volatile("cp.async.commit_group;" ::: "memory");
}
__device__ __forceinline__ void cpa_wait0() {
    asm volatile("cp.async.wait_group 0;" ::: "memory");
}
__device__ __forceinline__ void fsplit(float v, bf16& h, bf16& l) {
    h = __float2bfloat16(v);
    l = __float2bfloat16(v - __bfloat162float(h));
}

// ---------------- fused weight transpose + split (up to 4 weights) ----------
struct WSDesc { const float* W; bf16* H; bf16* L; int R, C, nz; };

__global__ void wsplit_multi(WSDesc d0, WSDesc d1, WSDesc d2, WSDesc d3,
                             int nb0, int nb1, int nb2, int nb3) {
    __shared__ float ts[32][33];
    int id = blockIdx.x;
    WSDesc d;
    if (id < nb0) { d = d0; }
    else if (id < nb0 + nb1) { d = d1; id -= nb0; }
    else if (id < nb0 + nb1 + nb2) { d = d2; id -= nb0 + nb1; }
    else { d = d3; id -= nb0 + nb1 + nb2; }
    int nbx = d.C >> 5, nby = d.R >> 5;
    int z = id / (nbx * nby);
    int rem = id - z * nbx * nby;
    int by = rem / nbx, bx = rem - by * nbx;
    size_t mo = (size_t)z * d.R * d.C;
    int c0 = bx * 32, r0 = by * 32;
    int tx = threadIdx.x, ty = threadIdx.y;
    #pragma unroll
    for (int i = 0; i < 4; ++i) {
        int r = r0 + ty + i * 8;
        ts[ty + i * 8][tx] = d.W[mo + (size_t)r * d.C + c0 + tx];
    }
    __syncthreads();
    #pragma unroll
    for (int i = 0; i < 4; ++i) {
        int n = c0 + ty + i * 8;
        int k = r0 + tx;
        float v = ts[tx][ty + i * 8];
        bf16 h = __float2bfloat16(v);
        d.H[mo + (size_t)n * d.R + k] = h;
        if (d.L)
            d.L[mo + (size_t)n * d.R + k] = __float2bfloat16(v - __bfloat162float(h));
    }
}

// ---------------- unified bf16 hi/lo tensor-core GEMM -----------------------
// OMODE 0: fp32 +bias/resid/relu | 1: scores | 3: bf16 linear | 5: fused QKV
// NPROD 3: ah*bh + ah*bl + al*bh | NPROD 1: ah*bh only (pure bf16)
// KCAUS: truncate K to (blockIdx.x+1)*128 (attn·V; wei is causal-zero beyond)
struct QKVP {
    const bf16 *bh0, *bl0, *bh1, *bl1, *bh2, *bl2;
    bf16 *ch0, *cl0, *ch1, *cl1, *ch2, *cl2;
};

template<int BN, int OMODE, int NPROD, bool KCAUS>
__global__ __launch_bounds__(256, 2)
void gmma_kernel(const bf16* __restrict__ Ah, const bf16* __restrict__ Al,
                 const bf16* __restrict__ Bhp, const bf16* __restrict__ Blp,
                 float* __restrict__ C, bf16* __restrict__ Chp, bf16* __restrict__ Clp,
                 const float* __restrict__ bias, const float* __restrict__ resid,
                 int relu, int K, int lda, int ldb, int ldc,
                 size_t aZh, size_t aZl, size_t bZh, size_t bZl,
                 size_t cZh, size_t cZl, QKVP qp) {
    constexpr int STR = 80;
    constexpr int ALO = 128 * STR;
    constexpr int BHO = 256 * STR;
    constexpr int BLO = BHO + BN * STR;
    constexpr int SSZ = BHO + 2 * BN * STR;
    constexpr int NT8 = BN / 32;
    constexpr int NB16 = NT8 / 2;
    constexpr int BSEG = BN * 4 / 256;
    extern __shared__ __align__(16) unsigned char smem[];

    int m0 = blockIdx.x * 128, n0 = blockIdx.y * BN;
    if (OMODE == 1 && n0 > m0) return;
    int z = blockIdx.z;
    const bf16 *Bh, *Bl = nullptr;
    bf16 *Ch = nullptr, *Cl = nullptr;
    if (OMODE == 5) {
        if (z == 0)      { Bh = qp.bh0; Bl = qp.bl0; Ch = qp.ch0; Cl = qp.cl0; }
        else if (z == 1) { Bh = qp.bh1; Bl = qp.bl1; Ch = qp.ch1; Cl = qp.cl1; }
        else             { Bh = qp.bh2; Bl = qp.bl2; Ch = qp.ch2; Cl = qp.cl2; }
    } else {
        Ah += (size_t)(z >> 4) * aZh + (size_t)(z & 15) * aZl;
        Al += (size_t)(z >> 4) * aZh + (size_t)(z & 15) * aZl;
        Bh = Bhp + (size_t)(z >> 4) * bZh + (size_t)(z & 15) * bZl;
        if (NPROD == 3) Bl = Blp + (size_t)(z >> 4) * bZh + (size_t)(z & 15) * bZl;
        if (OMODE == 0 || OMODE == 1)
            C += (size_t)(z >> 4) * cZh + (size_t)(z & 15) * cZl;
        else {
            Ch = Chp + (size_t)(z >> 4) * cZh + (size_t)(z & 15) * cZl;
            Cl = Clp + (size_t)(z >> 4) * cZh + (size_t)(z & 15) * cZl;
        }
    }

    int tid = threadIdx.x, lane = tid & 31, wid = tid >> 5;
    int wm = (wid & 1) * 64;
    int wn = (wid >> 1) * (BN / 4);

    float acc[4][NT8][4];
    #pragma unroll
    for (int i = 0; i < 4; ++i)
        #pragma unroll
        for (int j = 0; j < NT8; ++j)
            #pragma unroll
            for (int q = 0; q < 4; ++q) acc[i][j][q] = 0.f;

    uint32_t sbase = smem_u32(smem);
    int NC = KCAUS ? (blockIdx.x + 1) * 4 : (K / 32);

    auto load_stage = [&](int c) {
        uint32_t stg = sbase + (uint32_t)(c & 1) * SSZ;
        int kc = c * 32;
        #pragma unroll
        for (int i = 0; i < 2; ++i) {
            int slot = i * 256 + tid, r = slot >> 2, sg = slot & 3;
            uint32_t so = r * STR + sg * 16;
            size_t go = (size_t)(m0 + r) * lda + kc + sg * 8;
            cpa16(stg + so, Ah + go);
            if (NPROD >= 3) cpa16(stg + ALO + so, Al + go);
        }
        #pragma unroll
        for (int i = 0; i < BSEG; ++i) {
            int slot = i * 256 + tid, r = slot >> 2, sg = slot & 3;
            uint32_t so = r * STR + sg * 16;
            size_t go = (size_t)(n0 + r) * ldb + kc + sg * 8;
            cpa16(stg + BHO + so, Bh + go);
            if (NPROD == 3) cpa16(stg + BLO + so, Bl + go);
        }
        cpa_commit();
    };

    load_stage(0);
    uint32_t aAddr0 = sbase + (uint32_t)(wm + (lane & 15)) * STR + (lane >> 4) * 16;
    uint32_t bAddr0 = sbase + BHO + (uint32_t)(wn + (lane & 15)) * STR + (lane >> 4) * 16;

    for (int c = 0; c < NC; ++c) {
        cpa_wait0();
        __syncthreads();
        if (c + 1 < NC) load_stage(c + 1);
        uint32_t stg = (uint32_t)(c & 1) * SSZ;
        uint32_t aAddr = aAddr0 + stg, bAddr = bAddr0 + stg;
        #pragma unroll
        for (int ks = 0; ks < 2; ++ks) {
            uint32_t a[4][4];
            uint32_t bh[NT8][2], bl[NT8][2];
            #pragma unroll
            for (int g = 0; g < NB16; ++g) {
                uint32_t base = bAddr + g * 16 * STR + ks * 32;
                uint32_t r0, r1, r2, r3;
                ldsm4(r0, r1, r2, r3, base);
                bh[2*g][0] = r0; bh[2*g][1] = r2;
                bh[2*g+1][0] = r1; bh[2*g+1][1] = r3;
                if (NPROD == 3) {
                    ldsm4(r0, r1, r2, r3, base + BN * STR);
                    bl[2*g][0] = r0; bl[2*g][1] = r2;
                    bl[2*g+1][0] = r1; bl[2*g+1][1] = r3;
                }
            }
            #pragma unroll
            for (int mt = 0; mt < 4; ++mt) {
                uint32_t base = aAddr + mt * 16 * STR + ks * 32;
                ldsm4(a[mt][0], a[mt][1], a[mt][2], a[mt][3], base);
            }
            #pragma unroll
            for (int mt = 0; mt < 4; ++mt)
                #pragma unroll
                for (int n8 = 0; n8 < NT8; ++n8) {
                    mma16816(acc[mt][n8], a[mt], bh[n8]);
                    if (NPROD == 3) mma16816(acc[mt][n8], a[mt], bl[n8]);
                }
            if (NPROD >= 3) {
                #pragma unroll
                for (int mt = 0; mt < 4; ++mt) {
                    uint32_t base = aAddr + ALO + mt * 16 * STR + ks * 32;
                    ldsm4(a[mt][0], a[mt][1], a[mt][2], a[mt][3], base);
                }
                #pragma unroll
                for (int mt = 0; mt < 4; ++mt)
                    #pragma unroll
                    for (int n8 = 0; n8 < NT8; ++n8)
                        mma16816(acc[mt][n8], a[mt], bh[n8]);
            }
        }
    }

    int gid = lane >> 2, tig = lane & 3;
    #pragma unroll
    for (int mt = 0; mt < 4; ++mt) {
        #pragma unroll
        for (int n8 = 0; n8 < NT8; ++n8) {
            int colb = n0 + wn + n8 * 8 + tig * 2;
            #pragma unroll
            for (int h2 = 0; h2 < 2; ++h2) {
                int m = m0 + wm + mt * 16 + gid + h2 * 8;
                #pragma unroll
                for (int cc = 0; cc < 2; ++cc) {
                    int n = colb + cc;
                    float v = acc[mt][n8][h2 * 2 + cc];
                    if (OMODE == 0) {
                        if (bias) v += bias[n];
                        if (resid) v += resid[(size_t)m * ldc + n];
                        if (relu) v = fmaxf(v, 0.f);
                        C[(size_t)m * ldc + n] = v;
                    } else if (OMODE == 1) {
                        C[(size_t)m * ldc + n] = v * 0.125f;
                    } else if (OMODE == 3) {
                        if (bias) v += bias[n];
                        if (relu) v = fmaxf(v, 0.f);
                        bf16 h, l; fsplit(v, h, l);
                        Ch[(size_t)m * ldc + n] = h;
                        Cl[(size_t)m * ldc + n] = l;
                    } else {  // OMODE 5
                        int b = m >> 10, t = m & 1023;
                        bf16 h, l; fsplit(v, h, l);
                        if (z < 2) {   // q, k: [bh][t][64]
                            size_t o = (size_t)(((b * 16 + (n >> 6)) << 10) + t) * 64 + (n & 63);
                            Ch[o] = h; Cl[o] = l;
                        } else {       // v: [bh][s][t]
                            size_t o = ((size_t)((b * 16 + (n >> 6)) * 64 + (n & 63)) << 10) + t;
                            Ch[o] = h; Cl[o] = l;
                        }
                    }
                }
            }
        }
    }
}

__global__ void embed_kernel(const int* __restrict__ idx,
                             const float* __restrict__ tok,
                             const float* __restrict__ pos) {
    size_t i = (size_t)blockIdx.x * 256 + threadIdx.x;
    int d  = (int)(i & (Dd - 1));
    int bt = (int)(i >> 10);
    int t  = bt & (Tt - 1);
    g_x[i] = tok[(size_t)idx[bt] * Dd + d] + pos[(size_t)t * Dd + d];
}

// LN: float4 loads, warp-shuffle reduction, packed bf16x2 stores
__global__ void ln_kernel(const float* __restrict__ x,
                          const float* __restrict__ g,
                          const float* __restrict__ b,
                          bf16* __restrict__ oh, bf16* __restrict__ ol) {
    __shared__ float s1[8], s2[8];
    int row = blockIdx.x;
    int tid = threadIdx.x, lane = tid & 31, wrp = tid >> 5;
    const float4* xr = (const float4*)(x + (size_t)row * Dd);
    float4 v = xr[tid];
    float a  = v.x + v.y + v.z + v.w;
    float a2 = v.x*v.x + v.y*v.y + v.z*v.z + v.w*v.w;
    #pragma unroll
    for (int o = 16; o > 0; o >>= 1) {
        a  += __shfl_xor_sync(~0u, a, o);
        a2 += __shfl_xor_sync(~0u, a2, o);
    }
    if (lane == 0) { s1[wrp] = a; s2[wrp] = a2; }
    __syncthreads();
    a = 0.f; a2 = 0.f;
    #pragma unroll
    for (int w = 0; w < 8; ++w) { a += s1[w]; a2 += s2[w]; }
    float mean = a * (1.f / Dd);
    float var  = a2 * (1.f / Dd) - mean * mean;
    float rstd = rsqrtf(var + EPSf);
    float4 gv = ((const float4*)g)[tid];
    float4 bv = ((const float4*)b)[tid];
    float r0 = (v.x - mean) * rstd * gv.x + bv.x;
    float r1 = (v.y - mean) * rstd * gv.y + bv.y;
    float r2 = (v.z - mean) * rstd * gv.z + bv.z;
    float r3 = (v.w - mean) * rstd * gv.w + bv.w;
    bf16 h0,l0,h1,l1,h2,l2,h3,l3;
    fsplit(r0,h0,l0); fsplit(r1,h1,l1); fsplit(r2,h2,l2); fsplit(r3,h3,l3);
    __nv_bfloat162 hv0{h0,h1}, hv1{h2,h3}, lv0{l0,l1}, lv1{l2,l3};
    uint2 hp, lp;
    hp.x = *(uint32_t*)&hv0; hp.y = *(uint32_t*)&hv1;
    lp.x = *(uint32_t*)&lv0; lp.y = *(uint32_t*)&lv1;
    ((uint2*)(oh + (size_t)row * Dd))[tid] = hp;
    ((uint2*)(ol + (size_t)row * Dd))[tid] = lp;
}

__global__ void softmax_kernel(float* __restrict__ attnL,
                               bf16* __restrict__ WH, bf16* __restrict__ WL) {
    __shared__ float sm[8];
    int rgl = blockIdx.x;
    int bh = rgl >> 10, t = rgl & (Tt - 1);
    size_t off = ((size_t)bh << 20) + ((size_t)t << 10);
    float* p = attnL + off;
    bf16* wh = WH + off;
    bf16* wl = WL + off;
    int tid = threadIdx.x, lane = tid & 31, wrp = tid >> 5;
    float v[4];
    float mx = -3.4e38f;
    #pragma unroll
    for (int k = 0; k < 4; ++k) {
        int i = k * 256 + tid;
        float x = p[i];
        v[k] = (i <= t) ? x : -3.4e38f;
        mx = fmaxf(mx, v[k]);
    }
    #pragma unroll
    for (int o = 16; o > 0; o >>= 1) mx = fmaxf(mx, __shfl_xor_sync(~0u, mx, o));
    if (lane == 0) sm[wrp] = mx;
    __syncthreads();
    mx = sm[0];
    #pragma unroll
    for (int w = 1; w < 8; ++w) mx = fmaxf(mx, sm[w]);
    float e[4], s = 0.f;
    #pragma unroll
    for (int k = 0; k < 4; ++k) {
        int i = k * 256 + tid;
        e[k] = (i <= t) ? __expf(v[k] - mx) : 0.f;
        s += e[k];
    }
    #pragma unroll
    for (int o = 16; o > 0; o >>= 1) s += __shfl_xor_sync(~0u, s, o);
    __syncthreads();
    if (lane == 0) sm[wrp] = s;
    __syncthreads();
    s = 0.f;
    #pragma unroll
    for (int w = 0; w < 8; ++w) s += sm[w];
    float inv = 1.f / s;
    #pragma unroll
    for (int k = 0; k < 4; ++k) {
        int i = k * 256 + tid;
        float r = e[k] * inv;
        p[i] = r;
        bf16 h, l; fsplit(r, h, l);
        wh[i] = h; wl[i] = l;
    }
}

__global__ void loss_row_kernel(const int* __restrict__ targets) {
    __shared__ float sd[8];
    int r = blockIdx.x;
    const float4* p4 = (const float4*)(g_logits + (size_t)r * Vv);
    int tid = threadIdx.x, lane = tid & 31, wrp = tid >> 5;
    float mx = -3.4e38f;
    for (int i = tid; i < Vv / 4; i += 256) {
        float4 v = p4[i];
        mx = fmaxf(fmaxf(mx, fmaxf(v.x, v.y)), fmaxf(v.z, v.w));
    }
    #pragma unroll
    for (int o = 16; o > 0; o >>= 1) mx = fmaxf(mx, __shfl_xor_sync(~0u, mx, o));
    if (lane == 0) sd[wrp] = mx;
    __syncthreads();
    mx = sd[0];
    #pragma unroll
    for (int w = 1; w < 8; ++w) mx = fmaxf(mx, sd[w]);
    __syncthreads();
    float sum = 0.f;
    for (int i = tid; i < Vv / 4; i += 256) {
        float4 v = p4[i];
        sum += __expf(v.x - mx) + __expf(v.y - mx) + __expf(v.z - mx) + __expf(v.w - mx);
    }
    #pragma unroll
    for (int o = 16; o > 0; o >>= 1) sum += __shfl_xor_sync(~0u, sum, o);
    if (lane == 0) sd[wrp] = sum;
    __syncthreads();
    if (tid == 0) {
        float s = 0.f;
        #pragma unroll
        for (int w = 0; w < 8; ++w) s += sd[w];
        g_rownll[r] = logf(s) + mx - g_logits[(size_t)r * Vv + targets[r]];
    }
}

__global__ void loss_final_kernel(float* __restrict__ out) {
    __shared__ float sd[256];
    int tid = threadIdx.x;
    float s = 0.f;
    for (int i = tid; i < BT; i += 256) s += g_rownll[i];
    sd[tid] = s; __syncthreads();
    for (int st = 128; st > 0; st >>= 1) {
        if (tid < st) sd[tid] += sd[tid + st];
        __syncthreads();
    }
    if (tid == 0) out[0] = sd[0] * (1.f / BT);
}

#define SM128 (2 * ((256 + 2 * 128) * 80))
#define SM64  (2 * ((256 + 2 * 64) * 80))

extern "C" void kernel_launch(void* const* d_in, const int* in_sizes, int n_in,
                              void* d_out, int out_size) {
    (void)in_sizes; (void)n_in; (void)out_size;
    const int*   idx     = (const int*)d_in[0];
    const int*   targets = (const int*)d_in[1];
    const float* tok     = (const float*)d_in[2];
    const float* pos     = (const float*)d_in[3];
    const float* ln1_g   = (const float*)d_in[4];
    const float* ln1_b   = (const float*)d_in[5];
    const float* Wq      = (const float*)d_in[6];
    const float* Wk      = (const float*)d_in[7];
    const float* Wv      = (const float*)d_in[8];
    const float* Wp      = (const float*)d_in[9];
    const float* bp      = (const float*)d_in[10];
    const float* ln2_g   = (const float*)d_in[11];
    const float* ln2_b   = (const float*)d_in[12];
    const float* W1      = (const float*)d_in[13];
    const float* b1      = (const float*)d_in[14];
    const float* W2      = (const float*)d_in[15];
    const float* b2      = (const float*)d_in[16];
    const float* lnf_g   = (const float*)d_in[17];
    const float* lnf_b   = (const float*)d_in[18];
    const float* Wlm     = (const float*)d_in[19];
    const float* blm     = (const float*)d_in[20];

    float* out  = (float*)d_out;
    float* attn = out + 1;

    cudaFuncSetAttribute(gmma_kernel<128, 0, 3, false>, cudaFuncAttributeMaxDynamicSharedMemorySize, SM128);
    cudaFuncSetAttribute(gmma_kernel<128, 0, 1, false>, cudaFuncAttributeMaxDynamicSharedMemorySize, SM128);
    cudaFuncSetAttribute(gmma_kernel<128, 1, 3, false>, cudaFuncAttributeMaxDynamicSharedMemorySize, SM128);
    cudaFuncSetAttribute(gmma_kernel<128, 3, 3, false>, cudaFuncAttributeMaxDynamicSharedMemorySize, SM128);
    cudaFuncSetAttribute(gmma_kernel<128, 5, 3, false>, cudaFuncAttributeMaxDynamicSharedMemorySize, SM128);
    cudaFuncSetAttribute(gmma_kernel<64,  3, 3, true >, cudaFuncAttributeMaxDynamicSharedMemorySize, SM64);

    float *px, *plog;
    cudaGetSymbolAddress((void**)&px,   g_x);
    cudaGetSymbolAddress((void**)&plog, g_logits);
    bf16 *hH,*hL,*qH,*qL,*kH,*kL,*vH,*vL,*oH,*oL,*fH,*fL,*wH,*wL;
    cudaGetSymbolAddress((void**)&hH, g_hH); cudaGetSymbolAddress((void**)&hL, g_hL);
    cudaGetSymbolAddress((void**)&qH, g_qH); cudaGetSymbolAddress((void**)&qL, g_qL);
    cudaGetSymbolAddress((void**)&kH, g_kH); cudaGetSymbolAddress((void**)&kL, g_kL);
    cudaGetSymbolAddress((void**)&vH, g_vH); cudaGetSymbolAddress((void**)&vL, g_vL);
    cudaGetSymbolAddress((void**)&oH, g_oH); cudaGetSymbolAddress((void**)&oL, g_oL);
    cudaGetSymbolAddress((void**)&fH, g_ffH); cudaGetSymbolAddress((void**)&fL, g_ffL);
    cudaGetSymbolAddress((void**)&wH, g_wH); cudaGetSymbolAddress((void**)&wL, g_wL);
    bf16 *wqh,*wql,*wkh,*wkl,*wvh,*wvl,*wph,*wpl,*w1h,*w1l,*w2h,*w2l,*wlh;
    cudaGetSymbolAddress((void**)&wqh, g_wqT_h); cudaGetSymbolAddress((void**)&wql, g_wqT_l);
    cudaGetSymbolAddress((void**)&wkh, g_wkT_h); cudaGetSymbolAddress((void**)&wkl, g_wkT_l);
    cudaGetSymbolAddress((void**)&wvh, g_wvT_h); cudaGetSymbolAddress((void**)&wvl, g_wvT_l);
    cudaGetSymbolAddress((void**)&wph, g_wpT_h); cudaGetSymbolAddress((void**)&wpl, g_wpT_l);
    cudaGetSymbolAddress((void**)&w1h, g_w1T_h); cudaGetSymbolAddress((void**)&w1l, g_w1T_l);
    cudaGetSymbolAddress((void**)&w2h, g_w2T_h); cudaGetSymbolAddress((void**)&w2l, g_w2T_l);
    cudaGetSymbolAddress((void**)&wlh, g_wlmT_h);

    {
        WSDesc a0{Wq, wqh, wql, Dd, HSs, Ll*Hh};
        WSDesc a1{Wk, wkh, wkl, Dd, HSs, Ll*Hh};
        WSDesc a2{Wv, wvh, wvl, Dd, HSs, Ll*Hh};
        WSDesc a3{Wp, wph, wpl, Dd, Dd,  Ll};
        int nb0 = (HSs/32)*(Dd/32)*Ll*Hh, nb3 = (Dd/32)*(Dd/32)*Ll;
        wsplit_multi<<<nb0*3 + nb3, dim3(32, 8)>>>(a0, a1, a2, a3, nb0, nb0, nb0, nb3);
        WSDesc b0{W1, w1h, w1l, Dd, FFf, Ll};
        WSDesc b1{W2, w2h, w2l, FFf, Dd, Ll};
        WSDesc b2{Wlm, wlh, nullptr, Dd, Vv, 1};
        WSDesc b3{Wlm, wlh, nullptr, Dd, Vv, 0};
        int m0n = (FFf/32)*(Dd/32)*Ll, m1n = (Dd/32)*(FFf/32)*Ll, m2n = (Vv/32)*(Dd/32);
        wsplit_multi<<<m0n + m1n + m2n, dim3(32, 8)>>>(b0, b1, b2, b3, m0n, m1n, m2n, 0);
    }

    embed_kernel<<<BT * Dd / 256, 256>>>(idx, tok, pos);

    QKVP qpz{};
    const size_t WQL = (size_t)Hh * HSs * Dd;
    for (int l = 0; l < Ll; ++l) {
        float* attnL = attn + (size_t)l * Bb * Hh * Tt * Tt;

        ln_kernel<<<BT, 256>>>(px, ln1_g + (size_t)l * Dd, ln1_b + (size_t)l * Dd, hH, hL);

        QKVP qp{wqh + l * WQL, wql + l * WQL,
                wkh + l * WQL, wkl + l * WQL,
                wvh + l * WQL, wvl + l * WQL,
                qH, qL, kH, kL, vH, vL};
        gmma_kernel<128, 5, 3, false><<<dim3(32, 8, 3), 256, SM128>>>(
            hH, hL, nullptr, nullptr, nullptr, nullptr, nullptr,
            nullptr, nullptr, 0, Dd, Dd, Dd, Dd, 0, 0, 0, 0, 0, 0, qp);

        gmma_kernel<128, 1, 3, false><<<dim3(8, 8, Bb * Hh), 256, SM128>>>(
            qH, qL, kH, kL, attnL, nullptr, nullptr, nullptr, nullptr, 0,
            HSs, HSs, HSs, Tt,
            (size_t)16 * Tt * HSs, (size_t)Tt * HSs,
            (size_t)16 * Tt * HSs, (size_t)Tt * HSs,
            (size_t)16 * Tt * Tt, (size_t)Tt * Tt, qpz);

        softmax_kernel<<<Bb * Hh * Tt, 256>>>(attnL, wH, wL);

        gmma_kernel<64, 3, 3, true><<<dim3(8, 1, Bb * Hh), 256, SM64>>>(
            wH, wL, vH, vL, nullptr, oH, oL, nullptr, nullptr, 0,
            Tt, Tt, Tt, Dd,
            (size_t)16 * Tt * Tt, (size_t)Tt * Tt,
            (size_t)16 * HSs * Tt, (size_t)HSs * Tt,
            (size_t)Tt * Dd, HSs, qpz);

        gmma_kernel<128, 0, 3, false><<<dim3(32, 8, 1), 256, SM128>>>(
            oH, oL, wph + (size_t)l * Dd * Dd, wpl + (size_t)l * Dd * Dd,
            px, nullptr, nullptr, bp + (size_t)l * Dd, px, 0,
            Dd, Dd, Dd, Dd, 0, 0, 0, 0, 0, 0, qpz);

        ln_kernel<<<BT, 256>>>(px, ln2_g + (size_t)l * Dd, ln2_b + (size_t)l * Dd, hH, hL);

        gmma_kernel<128, 3, 3, false><<<dim3(32, 32, 1), 256, SM128>>>(
            hH, hL, w1h + (size_t)l * Dd * FFf, w1l + (size_t)l * Dd * FFf,
            nullptr, fH, fL, b1 + (size_t)l * FFf, nullptr, 1,
            Dd, Dd, Dd, FFf, 0, 0, 0, 0, 0, 0, qpz);

        gmma_kernel<128, 0, 3, false><<<dim3(32, 8, 1), 256, SM128>>>(
            fH, fL, w2h + (size_t)l * FFf * Dd, w2l + (size_t)l * FFf * Dd,
            px, nullptr, nullptr, b2 + (size_t)l * Dd, px, 0,
            FFf, FFf, FFf, Dd, 0, 0, 0, 0, 0, 0, qpz);
    }

    ln_kernel<<<BT, 256>>>(px, lnf_g, lnf_b, hH, hL);

    // LM head: 1-product pure bf16 — feeds only the scalar loss
    gmma_kernel<128, 0, 1, false><<<dim3(32, 250, 1), 256, SM128>>>(
        hH, hL, wlh, nullptr, plog, nullptr, nullptr, blm, nullptr, 0,
        Dd, Dd, Dd, Vv, 0, 0, 0, 0, 0, 0, qpz);

    loss_row_kernel<<<BT, 256>>>(targets);
    loss_final_kernel<<<1, 256>>>(out);
}